// round 14
// baseline (speedup 1.0000x reference)
#include <cuda_runtime.h>
#include <cuda.h>
#include <cuda_bf16.h>
#include <math.h>
#include <stdint.h>
#include <dlfcn.h>

#define Bq 8
#define Lq 128
#define Bp 64
#define Lp 512
#define Hd 1024
#define MQ (Bq*(Lq-1))   /* 1016  */
#define MP (Bp*(Lp-1))   /* 32704 */
#define QTILES 8
#define PTILES 256
#define INV_TEMP 50.0f

#define KS   64
#define NSTG (Hd/KS)          /* 16 */
#define ROWB 128              /* SW128-swizzled rows */
#define TILEB (128*ROWB)      /* 16384 B */
#define STGB  (2*TILEB)       /* 32768 B */
#define NPIPE 3
#define RED_OFF  (NPIPE*STGB)      /* 98304 */
#define RSQP_OFF (RED_OFF + 1024)
#define MBAR_OFF (RSQP_OFF + 512)  /* FB0..2, EB0..2 (8B each) */
#define SMEM_TOTAL (MBAR_OFF + 64)

/* work queue */
#define NTQ  64                /* Q projection tiles  */
#define NTP  2048              /* P projection tiles  */
#define NTMS 2048              /* maxsim tiles        */
#define NTOT (NTQ+NTP+NTMS)

/* ---------------- scratch (allocation-free: device globals) ---------------- */
__device__ float g_tw_q[Bq*Lq];
__device__ float g_wq[Bq*Lq];
__device__ float g_tw_p[Bp*Lp];
__device__ float g_wp[Bp*Lp];
__device__ float g_qmax[(size_t)MQ*Bp*4];
__device__ float g_ssq_q[MQ*16];
__device__ float g_ssq_p[(size_t)MP*16];
__device__ int   g_sync[2+PTILES];   /* [0]=ticket, [1]=qdone, [2+py]=pdone */
__device__ __align__(256) __nv_bfloat16 g_qh_bf[(size_t)MQ*Hd];
__device__ __align__(256) __nv_bfloat16 g_ph_bf[(size_t)MP*Hd];
__device__ __align__(256) __nv_bfloat16 g_w_bf[(size_t)Hd*Hd];
__device__ __align__(256) __nv_bfloat16 g_Qcb[(size_t)MQ*Hd];
__device__ __align__(256) __nv_bfloat16 g_Pcb[(size_t)MP*Hd];
__device__ __align__(128) CUtensorMap g_map_aq, g_map_ap, g_map_w, g_map_q, g_map_p;

/* ---------------- helpers ---------------- */
__device__ __forceinline__ uint32_t sw128(uint32_t o){ return o ^ ((o>>3)&0x70u); }

__device__ __forceinline__ void mma_bf16(float* c, const unsigned* a, const unsigned* b){
    asm volatile("mma.sync.aligned.m16n8k16.row.col.f32.bf16.bf16.f32 "
        "{%0,%1,%2,%3}, {%4,%5,%6,%7}, {%8,%9}, {%0,%1,%2,%3};"
        : "+f"(c[0]), "+f"(c[1]), "+f"(c[2]), "+f"(c[3])
        : "r"(a[0]), "r"(a[1]), "r"(a[2]), "r"(a[3]), "r"(b[0]), "r"(b[1]));
}
__device__ __forceinline__ void ldm_x4(unsigned& r0, unsigned& r1, unsigned& r2, unsigned& r3, unsigned addr){
    asm volatile("ldmatrix.sync.aligned.m8n8.x4.shared.b16 {%0,%1,%2,%3}, [%4];"
        : "=r"(r0), "=r"(r1), "=r"(r2), "=r"(r3) : "r"(addr));
}
__device__ __forceinline__ void tma2d(unsigned dst, const CUtensorMap* map, int x, int y, unsigned mbar){
    asm volatile("cp.async.bulk.tensor.2d.shared::cluster.global.tile.mbarrier::complete_tx::bytes "
                 "[%0], [%1, {%2, %3}], [%4];"
                 :: "r"(dst), "l"(map), "r"(x), "r"(y), "r"(mbar) : "memory");
}
#define TMA_PREFETCH(map) asm volatile("prefetch.tensormap [%0];" :: "l"(map))
#define MBARRIER_INIT(addr, cnt) \
    asm volatile("mbarrier.init.shared.b64 [%0], %1;" :: "r"(addr), "r"(cnt) : "memory")
#define MBARRIER_EXPECT_TX(addr, bytes) \
    asm volatile("mbarrier.arrive.expect_tx.shared.b64 _, [%0], %1;" :: "r"(addr), "r"(bytes) : "memory")
#define MBARRIER_ARRIVE(addr) \
    asm volatile("mbarrier.arrive.shared.b64 _, [%0];" :: "r"(addr) : "memory")
#define MB_WAIT(mbar, parity) do{                                                   \
    uint32_t _done;                                                                 \
    asm volatile("{\n\t.reg .pred p;\n\t"                                           \
        "mbarrier.try_wait.parity.acquire.cta.shared::cta.b64 p, [%1], %2;\n\t"     \
        "selp.b32 %0, 1, 0, p;\n\t}" : "=r"(_done) : "r"(mbar), "r"(parity) : "memory"); \
    while(!_done){                                                                  \
        asm volatile("{\n\t.reg .pred p;\n\t"                                       \
            "mbarrier.try_wait.parity.acquire.cta.shared::cta.b64 p, [%1], %2, 0x989680;\n\t" \
            "selp.b32 %0, 1, 0, p;\n\t}" : "=r"(_done) : "r"(mbar), "r"(parity) : "memory"); \
    }                                                                               \
}while(0)

/* producer issue of pipeline stage n (buffer n%3). Call under tid==0. */
#define PIPE_ISSUE(n_, mA_, ya_, mB_, yb_, k0_) do{                              \
    int buf_ = (n_)%NPIPE;                                                       \
    if ((n_) >= NPIPE){                                                          \
        MB_WAIT(sb+MBAR_OFF+24+(unsigned)buf_*8, (int)((ephbits>>buf_)&1u));     \
        ephbits ^= (1u<<buf_);                                                   \
    }                                                                            \
    unsigned st_ = sb + (unsigned)buf_*STGB;                                     \
    unsigned mb_ = sb + MBAR_OFF + (unsigned)buf_*8;                             \
    MBARRIER_EXPECT_TX(mb_, (unsigned)STGB);                                     \
    tma2d(st_,         mA_, k0_, ya_, mb_);                                      \
    tma2d(st_ + TILEB, mB_, k0_, yb_, mb_);                                      \
}while(0)

/* K=64 stage for warp tile 64x64, SW128-swizzled smem */
__device__ __forceinline__ void mma_stage64(unsigned abase, unsigned bbase,
                                            int lane, int wm, int wn, float acc[4][8][4])
{
    #pragma unroll
    for (int k=0;k<4;k++){
        int klo = k*16;
        unsigned a[4][4];
        int m_i = lane>>3;
        int arow = ((m_i&1)<<3) + (lane&7);
        int acol = klo + ((m_i>>1)<<3);
        #pragma unroll
        for (int mt=0; mt<4; mt++){
            unsigned addr = abase + sw128((unsigned)((wm*64 + mt*16 + arow)*ROWB + acol*2));
            ldm_x4(a[mt][0], a[mt][1], a[mt][2], a[mt][3], addr);
        }
        unsigned b[4][4];
        int brow = (lane&7) + ((lane>>4)<<3);
        int bcol = klo + (((lane>>3)&1)<<3);
        #pragma unroll
        for (int bpi=0; bpi<4; bpi++){
            unsigned addr = bbase + sw128((unsigned)((wn*64 + bpi*16 + brow)*ROWB + bcol*2));
            ldm_x4(b[bpi][0], b[bpi][1], b[bpi][2], b[bpi][3], addr);
        }
        #pragma unroll
        for (int mt=0; mt<4; mt++)
            #pragma unroll
            for (int nt=0; nt<8; nt++)
                mma_bf16(acc[mt][nt], a[mt], &b[nt>>1][(nt&1)*2]);
    }
}

/* ---------------- persistent fused GEMM: proj tiles then maxsim tiles ---------------- */
__global__ void __launch_bounds__(128,2)
fused_gemm(const CUtensorMap* __restrict__ mapAq, const CUtensorMap* __restrict__ mapAp,
           const CUtensorMap* __restrict__ mapW,
           const CUtensorMap* __restrict__ mapQ, const CUtensorMap* __restrict__ mapP,
           __nv_bfloat16* __restrict__ Cq, __nv_bfloat16* __restrict__ Cp,
           float* __restrict__ ssq_q, float* __restrict__ ssq_p,
           const float* __restrict__ bias,
           const float* __restrict__ maskq, const float* __restrict__ maskp,
           float* __restrict__ qmax4)
{
    extern __shared__ __align__(1024) char smem[];
    unsigned sb = (unsigned)__cvta_generic_to_shared(smem);
    float* red  = (float*)(smem + RED_OFF);
    float* rsqs = (float*)(smem + RSQP_OFF);
    __shared__ int s_t;
    int tid = threadIdx.x, lane = tid&31, wid = tid>>5;
    int wm = wid>>1, wn = wid&1;

    if (tid==0){
        TMA_PREFETCH(mapAq); TMA_PREFETCH(mapAp); TMA_PREFETCH(mapW);
        TMA_PREFETCH(mapQ);  TMA_PREFETCH(mapP);
        MBARRIER_INIT(sb+MBAR_OFF,    1u);
        MBARRIER_INIT(sb+MBAR_OFF+8,  1u);
        MBARRIER_INIT(sb+MBAR_OFF+16, 1u);
        MBARRIER_INIT(sb+MBAR_OFF+24, 128u);
        MBARRIER_INIT(sb+MBAR_OFF+32, 128u);
        MBARRIER_INIT(sb+MBAR_OFF+40, 128u);
    }
    __syncthreads();

    int gs = 0;                 /* global consumed-stage counter (continuous pipeline) */
    unsigned ephbits = 0;       /* EB parity bits (tid0 only meaningful) */

    for (;;){
        if (tid==0) s_t = atomicAdd(&g_sync[0], 1);
        __syncthreads();
        int t = s_t;
        if (t >= NTOT) break;

        if (t < NTQ+NTP){
            /* ---------------- projection tile ---------------- */
            bool isQ = t < NTQ;
            int py, xb;
            if (isQ){ py = t>>3; xb = t&7; }
            else    { int u = t-NTQ; py = u>>3; xb = u&7; }
            const CUtensorMap* mapA = isQ ? mapAq : mapAp;
            __nv_bfloat16* Cb = isQ ? Cq : Cp;
            float* ssq = isQ ? ssq_q : ssq_p;
            const float* mask = isQ ? maskq : maskp;
            int M  = isQ ? MQ : MP;
            int La = isQ ? Lq : Lp;
            int Lm1 = La - 1;
            int blkM = py*128, blkN = xb*128;

            float acc[4][8][4];
            #pragma unroll
            for (int mt=0;mt<4;mt++) for (int nt=0;nt<8;nt++) for (int j=0;j<4;j++) acc[mt][nt][j]=0.f;

            if (tid==0){
                PIPE_ISSUE(gs+0, mapA, blkM, mapW, blkN, 0);
                PIPE_ISSUE(gs+1, mapA, blkM, mapW, blkN, KS);
            }
            #pragma unroll 1
            for (int s=0; s<NSTG; s++){
                if (s+2 < NSTG && tid==0)
                    PIPE_ISSUE(gs+s+2, mapA, blkM, mapW, blkN, (s+2)*KS);
                int m = gs + s;
                int cb = m%NPIPE, fph = (m/NPIPE)&1;
                MB_WAIT(sb + MBAR_OFF + (unsigned)cb*8, fph);
                unsigned cs = sb + (unsigned)cb*STGB;
                mma_stage64(cs, cs + TILEB, lane, wm, wn, acc);
                MBARRIER_ARRIVE(sb + MBAR_OFF + 24 + (unsigned)cb*8);
            }
            gs += NSTG;

            /* epilogue: bias + mask, partial sumsq, bf16 store (unnormalized) */
            #pragma unroll
            for (int mt=0;mt<4;mt++){
                #pragma unroll
                for (int half=0; half<2; half++){
                    int gr = blkM + wm*64 + mt*16 + (lane>>2) + half*8;
                    bool valid = gr < M;
                    float m = 0.f;
                    if (valid) m = mask[(gr/Lm1)*La + gr%Lm1 + 1];
                    float ss = 0.f;
                    #pragma unroll
                    for (int nt=0;nt<8;nt++){
                        int gc = blkN + wn*64 + nt*8 + 2*(lane&3);
                        float v0 = (acc[mt][nt][half*2+0] + bias[gc])   * m;
                        float v1 = (acc[mt][nt][half*2+1] + bias[gc+1]) * m;
                        ss = fmaf(v0,v0, fmaf(v1,v1, ss));
                        if (valid){
                            __nv_bfloat162 bv = __floats2bfloat162_rn(v0, v1);
                            *(__nv_bfloat162*)(Cb + (size_t)gr*Hd + gc) = bv;
                        }
                    }
                    ss += __shfl_xor_sync(0xffffffffu, ss, 1);
                    ss += __shfl_xor_sync(0xffffffffu, ss, 2);
                    if (valid && (lane&3)==0)
                        ssq[(size_t)gr*16 + xb*2 + wn] = ss;
                }
            }
            __threadfence();
            __syncthreads();
            if (tid==0){
                if (isQ) atomicAdd(&g_sync[1], 1);
                else     atomicAdd(&g_sync[2+py], 1);
            }
        } else {
            /* ---------------- maxsim tile ---------------- */
            int u = t - (NTQ+NTP);
            int pbi = u>>5, rem = u&31, qc = rem>>3, qtile = rem&7;
            int blkM = qtile*128;
            int brow0 = pbi*(Lp-1) + qc*128;
            int bvv = (Lp-1) - qc*128; if (bvv > 128) bvv = 128;
            int py0 = brow0>>7, py1 = (brow0+127)>>7;

            if (tid==0){
                while (atomicAdd(&g_sync[1], 0) < NTQ) __nanosleep(128);
                while (atomicAdd(&g_sync[2+py0], 0) < 8) __nanosleep(128);
                while (atomicAdd(&g_sync[2+py1], 0) < 8) __nanosleep(128);
                __threadfence();
            }
            __syncthreads();

            /* per-passage-token reciprocal norms */
            if (tid < bvv){
                const float* sp = ssq_p + ((long)brow0 + tid)*16;
                float tt = 0.f;
                #pragma unroll
                for (int k=0;k<16;k++) tt += sp[k];
                rsqs[tid] = 1.0f / fmaxf(sqrtf(tt), 1e-12f);
            }
            __syncthreads();

            float acc[4][8][4];
            #pragma unroll
            for (int mt=0;mt<4;mt++) for (int nt=0;nt<8;nt++) for (int j=0;j<4;j++) acc[mt][nt][j]=0.f;

            if (tid==0){
                PIPE_ISSUE(gs+0, mapQ, blkM, mapP, brow0, 0);
                PIPE_ISSUE(gs+1, mapQ, blkM, mapP, brow0, KS);
            }
            #pragma unroll 1
            for (int s=0; s<NSTG; s++){
                if (s+2 < NSTG && tid==0)
                    PIPE_ISSUE(gs+s+2, mapQ, blkM, mapP, brow0, (s+2)*KS);
                int m = gs + s;
                int cb = m%NPIPE, fph = (m/NPIPE)&1;
                MB_WAIT(sb + MBAR_OFF + (unsigned)cb*8, fph);
                unsigned cs = sb + (unsigned)cb*STGB;
                mma_stage64(cs, cs + TILEB, lane, wm, wn, acc);
                MBARRIER_ARRIVE(sb + MBAR_OFF + 24 + (unsigned)cb*8);
            }
            gs += NSTG;

            /* fold with per-token reciprocal norm */
            float runmax[4][2];
            #pragma unroll
            for (int mt=0;mt<4;mt++){ runmax[mt][0]=-1e30f; runmax[mt][1]=-1e30f; }
            #pragma unroll
            for (int nt=0;nt<8;nt++){
                int c0 = wn*64 + nt*8 + 2*(lane&3);
                bool v0 = c0     < bvv;
                bool v1 = c0 + 1 < bvv;
                float sp0 = v0 ? rsqs[c0]   : 0.f;
                float sp1 = v1 ? rsqs[c0+1] : 0.f;
                #pragma unroll
                for (int mt=0;mt<4;mt++){
                    if (v0){
                        runmax[mt][0] = fmaxf(runmax[mt][0], acc[mt][nt][0]*sp0);
                        runmax[mt][1] = fmaxf(runmax[mt][1], acc[mt][nt][2]*sp0);
                    }
                    if (v1){
                        runmax[mt][0] = fmaxf(runmax[mt][0], acc[mt][nt][1]*sp1);
                        runmax[mt][1] = fmaxf(runmax[mt][1], acc[mt][nt][3]*sp1);
                    }
                }
            }
            #pragma unroll
            for (int mt=0;mt<4;mt++){
                #pragma unroll
                for (int h=0;h<2;h++){
                    runmax[mt][h] = fmaxf(runmax[mt][h], __shfl_xor_sync(0xffffffffu, runmax[mt][h], 1));
                    runmax[mt][h] = fmaxf(runmax[mt][h], __shfl_xor_sync(0xffffffffu, runmax[mt][h], 2));
                }
            }
            if ((lane&3)==0){
                #pragma unroll
                for (int mt=0;mt<4;mt++){
                    int row = wm*64 + mt*16 + (lane>>2);
                    red[row*2 + wn]     = runmax[mt][0];
                    red[(row+8)*2 + wn] = runmax[mt][1];
                }
            }
            __syncthreads();
            {
                int gr = blkM + tid;
                if (gr < MQ)
                    qmax4[(size_t)gr*(Bp*4) + (pbi*4 + qc)] = fmaxf(red[tid*2], red[tid*2+1]);
            }
            __syncthreads();
        }
    }
}

/* ---------------- merged f32->bf16 convert (compact, CLS-dropped) + sparse token weight ---------------- */
__global__ void cvt_tw_all(const float* __restrict__ qh, const float* __restrict__ ph,
                           const float* __restrict__ sw, const float* __restrict__ sbp,
                           __nv_bfloat16* __restrict__ qbf, __nv_bfloat16* __restrict__ pbf,
                           float* __restrict__ twq, float* __restrict__ twp)
{
    int row = blockIdx.x, tid = threadIdx.x;
    int lane = tid&31, wid = tid>>5;
    const float* h; __nv_bfloat16* o; float* tw; int r, L;
    if (row < Bq*Lq){ h = qh; o = qbf; tw = twq; r = row; L = Lq; }
    else            { r = row - Bq*Lq; h = ph; o = pbf; tw = twp; L = Lp; }
    int b = r / L, t = r % L;
    const float* hp = h + (size_t)r*Hd + tid*8;
    float4 a = *(const float4*)hp;
    float4 bb = *(const float4*)(hp+4);
    const float* w = sw + tid*8;
    float4 wa = *(const float4*)w;
    float4 wb = *(const float4*)(w+4);
    if (t > 0){
        int cr = b*(L-1) + (t-1);
        uint4 ov;
        __nv_bfloat162 p0 = __floats2bfloat162_rn(a.x, a.y);
        __nv_bfloat162 p1 = __floats2bfloat162_rn(a.z, a.w);
        __nv_bfloat162 p2 = __floats2bfloat162_rn(bb.x, bb.y);
        __nv_bfloat162 p3 = __floats2bfloat162_rn(bb.z, bb.w);
        ov.x = *(unsigned*)&p0; ov.y = *(unsigned*)&p1; ov.z = *(unsigned*)&p2; ov.w = *(unsigned*)&p3;
        *(uint4*)(o + (size_t)cr*Hd + tid*8) = ov;
    }
    float s = fmaf(a.x,wa.x, fmaf(a.y,wa.y, fmaf(a.z,wa.z, fmaf(a.w,wa.w,
              fmaf(bb.x,wb.x, fmaf(bb.y,wb.y, fmaf(bb.z,wb.z, bb.w*wb.w)))))));
    #pragma unroll
    for (int of=16;of;of>>=1) s += __shfl_xor_sync(0xffffffffu, s, of);
    __shared__ float ws[4];
    if (lane==0) ws[wid] = s;
    __syncthreads();
    if (tid==0) tw[r] = fmaxf(ws[0]+ws[1]+ws[2]+ws[3] + sbp[0], 0.f);
}

/* ---------------- f32 -> bf16 convert (weights only) ---------------- */
__global__ void f2bf_kernel(const float* __restrict__ in, __nv_bfloat16* __restrict__ out, int n4){
    int i = blockIdx.x*blockDim.x + threadIdx.x;
    if (i < n4){
        float4 v = *(const float4*)(in + (size_t)i*4);
        __nv_bfloat162 lo = __floats2bfloat162_rn(v.x, v.y);
        __nv_bfloat162 hi = __floats2bfloat162_rn(v.z, v.w);
        uint2 o; o.x = *(unsigned*)&lo; o.y = *(unsigned*)&hi;
        *(uint2*)(out + (size_t)i*4) = o;
    }
}

/* ---------------- dense: CLS cosine / TEMP ---------------- */
__global__ void dense_kernel(const float* __restrict__ qh, const float* __restrict__ ph,
                             float* __restrict__ out)
{
    int pb = blockIdx.x, qb = blockIdx.y, tid = threadIdx.x;
    const float* q = qh + (size_t)qb*Lq*Hd;
    const float* p = ph + (size_t)pb*Lp*Hd;
    float qq=0.f, pp=0.f, qp=0.f;
    for (int i=tid;i<Hd;i+=256){ float a=q[i], b=p[i];
        qq=fmaf(a,a,qq); pp=fmaf(b,b,pp); qp=fmaf(a,b,qp); }
    __shared__ float r0[256], r1[256], r2[256];
    r0[tid]=qq; r1[tid]=pp; r2[tid]=qp; __syncthreads();
    for (int o=128;o>0;o>>=1){
        if (tid<o){ r0[tid]+=r0[tid+o]; r1[tid]+=r1[tid+o]; r2[tid]+=r2[tid+o]; }
        __syncthreads();
    }
    if (tid==0){
        float d = fmaxf(sqrtf(r0[0]),1e-12f)*fmaxf(sqrtf(r1[0]),1e-12f);
        out[qb*Bp+pb] = r2[0]/d*INV_TEMP;
    }
}

/* ---------------- sparse dedup + scoring ---------------- */
__global__ void canon_kernel(const int* __restrict__ ids, const float* __restrict__ tw,
                             float* __restrict__ weff, int L)
{
    __shared__ int   sid[512];
    __shared__ float stw[512];
    int b = blockIdx.x, i = threadIdx.x;
    int base = b*L;
    sid[i] = ids[base+i]; stw[i] = tw[base+i];
    __syncthreads();
    float w = stw[i]; int id = sid[i];
    if (id < 4) w = 0.f;
    else {
        for (int j=0;j<L;j++){
            if (j!=i && sid[j]==id){
                float wj = stw[j];
                if (wj > w || (wj==w && j<i)) { w=0.f; break; }
            }
        }
    }
    weff[base+i] = w;
}

__global__ void sparse_score_kernel(const int* __restrict__ q_ids, const float* __restrict__ wq,
                                    const int* __restrict__ p_ids, const float* __restrict__ wp,
                                    float* __restrict__ out)
{
    __shared__ int   spid[Lp];
    __shared__ float spw[Lp];
    __shared__ float red[256];
    int pb=blockIdx.x, qb=blockIdx.y, tid=threadIdx.x;
    for (int j=tid;j<Lp;j+=256){ spid[j]=p_ids[pb*Lp+j]; spw[j]=wp[pb*Lp+j]; }
    __syncthreads();
    float s = 0.f;
    if (tid < Lq){
        int id = q_ids[qb*Lq+tid]; float w = wq[qb*Lq+tid];
        if (w > 0.f){
            for (int j=0;j<Lp;j++) if (spid[j]==id) s = fmaf(w, spw[j], s);
        }
    }
    red[tid]=s; __syncthreads();
    for (int o=128;o>0;o>>=1){ if (tid<o) red[tid]+=red[tid+o]; __syncthreads(); }
    if (tid==0) out[Bq*Bp + qb*Bp+pb] = red[0]*INV_TEMP;
}

__global__ void colbert_final_kernel(const float* __restrict__ qmax4,
                                     const float* __restrict__ ssq_q,
                                     const float* __restrict__ q_mask,
                                     float* __restrict__ out)
{
    int pb=blockIdx.x, qb=blockIdx.y, tid=threadIdx.x;  /* 128 threads */
    float v=0.f, mm=0.f;
    if (tid < Lq-1){
        int gr = qb*(Lq-1)+tid;
        const float* qm = qmax4 + (size_t)gr*(Bp*4) + pb*4;
        float m4 = fmaxf(fmaxf(qm[0],qm[1]), fmaxf(qm[2],qm[3]));
        float t = 0.f;
        #pragma unroll
        for (int k=0;k<16;k++) t += ssq_q[gr*16+k];
        v  = m4 / fmaxf(sqrtf(t), 1e-12f);
        mm = q_mask[qb*Lq + tid + 1];
    }
    __shared__ float rv[128], rm[128];
    rv[tid]=v; rm[tid]=mm; __syncthreads();
    for (int o=64;o>0;o>>=1){ if (tid<o){ rv[tid]+=rv[tid+o]; rm[tid]+=rm[tid+o]; } __syncthreads(); }
    if (tid==0) out[2*Bq*Bp + qb*Bp+pb] = rv[0]/rm[0]*INV_TEMP;
}

/* ---------------- host: tensor-map creation via dlopen'd driver API ---------------- */
typedef CUresult (*EncFn)(CUtensorMap*, CUtensorMapDataType, cuuint32_t, void*,
                          const cuuint64_t*, const cuuint64_t*, const cuuint32_t*,
                          const cuuint32_t*, CUtensorMapInterleave, CUtensorMapSwizzle,
                          CUtensorMapL2promotion, CUtensorMapFloatOOBfill);

static void make_map2d(EncFn enc, CUtensorMap* m, void* addr, unsigned long long d0, unsigned long long d1){
    cuuint64_t dims[2]    = {(cuuint64_t)d0, (cuuint64_t)d1};
    cuuint64_t strides[1] = {(cuuint64_t)(d0*2)};
    cuuint32_t box[2]     = {(cuuint32_t)KS, 128u};
    cuuint32_t es[2]      = {1u, 1u};
    enc(m, CU_TENSOR_MAP_DATA_TYPE_BFLOAT16, 2, addr, dims, strides, box, es,
        CU_TENSOR_MAP_INTERLEAVE_NONE, CU_TENSOR_MAP_SWIZZLE_128B,
        CU_TENSOR_MAP_L2_PROMOTION_L2_128B, CU_TENSOR_MAP_FLOAT_OOB_FILL_NONE);
}

/* ---------------- launcher ---------------- */
extern "C" void kernel_launch(void* const* d_in, const int* in_sizes, int n_in,
                              void* d_out, int out_size)
{
    const float* q_hidden  = (const float*)d_in[0];
    const float* p_hidden  = (const float*)d_in[1];
    const float* q_mask    = (const float*)d_in[2];
    const float* p_mask    = (const float*)d_in[3];
    const int*   q_ids     = (const int*)  d_in[4];
    const int*   p_ids     = (const int*)  d_in[5];
    const float* colbert_w = (const float*)d_in[6];
    const float* colbert_b = (const float*)d_in[7];
    const float* sparse_w  = (const float*)d_in[8];
    const float* sparse_b  = (const float*)d_in[9];
    float* out = (float*)d_out;

    static float *p_tw_q=nullptr,*p_wq=nullptr,*p_tw_p=nullptr,*p_wp=nullptr,
                 *p_qmax=nullptr,*p_ssq_q=nullptr,*p_ssq_p=nullptr;
    static int* p_sync=nullptr;
    static __nv_bfloat16 *p_qh=nullptr,*p_ph=nullptr,*p_w=nullptr,*p_Qcb=nullptr,*p_Pcb=nullptr;
    static CUtensorMap *pm_aq=nullptr,*pm_ap=nullptr,*pm_w=nullptr,*pm_q=nullptr,*pm_p=nullptr;
    static cudaStream_t s2 = nullptr;
    static cudaEvent_t evA = nullptr, evB = nullptr;
    if (!p_tw_q){
        cudaGetSymbolAddress((void**)&p_tw_q, g_tw_q);
        cudaGetSymbolAddress((void**)&p_wq,   g_wq);
        cudaGetSymbolAddress((void**)&p_tw_p, g_tw_p);
        cudaGetSymbolAddress((void**)&p_wp,   g_wp);
        cudaGetSymbolAddress((void**)&p_qmax, g_qmax);
        cudaGetSymbolAddress((void**)&p_ssq_q, g_ssq_q);
        cudaGetSymbolAddress((void**)&p_ssq_p, g_ssq_p);
        cudaGetSymbolAddress((void**)&p_sync,  g_sync);
        cudaGetSymbolAddress((void**)&p_qh,   g_qh_bf);
        cudaGetSymbolAddress((void**)&p_ph,   g_ph_bf);
        cudaGetSymbolAddress((void**)&p_w,    g_w_bf);
        cudaGetSymbolAddress((void**)&p_Qcb,  g_Qcb);
        cudaGetSymbolAddress((void**)&p_Pcb,  g_Pcb);
        cudaGetSymbolAddress((void**)&pm_aq,  g_map_aq);
        cudaGetSymbolAddress((void**)&pm_ap,  g_map_ap);
        cudaGetSymbolAddress((void**)&pm_w,   g_map_w);
        cudaGetSymbolAddress((void**)&pm_q,   g_map_q);
        cudaGetSymbolAddress((void**)&pm_p,   g_map_p);
        cudaFuncSetAttribute(fused_gemm, cudaFuncAttributeMaxDynamicSharedMemorySize, SMEM_TOTAL);
        cudaStreamCreateWithFlags(&s2, cudaStreamNonBlocking);
        cudaEventCreateWithFlags(&evA, cudaEventDisableTiming);
        cudaEventCreateWithFlags(&evB, cudaEventDisableTiming);

        /* build tensor maps once (first, uncaptured call) */
        void* h = dlopen("libcuda.so.1", RTLD_NOW | RTLD_GLOBAL);
        if (!h) h = dlopen("libcuda.so", RTLD_NOW | RTLD_GLOBAL);
        EncFn enc = (EncFn)dlsym(h, "cuTensorMapEncodeTiled");
        CUtensorMap hm_aq, hm_ap, hm_w, hm_q, hm_p;
        make_map2d(enc, &hm_aq, p_qh,  Hd, MQ);
        make_map2d(enc, &hm_ap, p_ph,  Hd, MP);
        make_map2d(enc, &hm_w,  p_w,   Hd, Hd);
        make_map2d(enc, &hm_q,  p_Qcb, Hd, MQ);
        make_map2d(enc, &hm_p,  p_Pcb, Hd, MP);
        cudaMemcpyToSymbol(g_map_aq, &hm_aq, sizeof(CUtensorMap));
        cudaMemcpyToSymbol(g_map_ap, &hm_ap, sizeof(CUtensorMap));
        cudaMemcpyToSymbol(g_map_w,  &hm_w,  sizeof(CUtensorMap));
        cudaMemcpyToSymbol(g_map_q,  &hm_q,  sizeof(CUtensorMap));
        cudaMemcpyToSymbol(g_map_p,  &hm_p,  sizeof(CUtensorMap));
    }

    dim3 gQP(Bp, Bq);

    /* main stream: reset work-queue state, converts */
    cudaMemsetAsync(p_sync, 0, sizeof(int)*(2+PTILES), 0);
    cvt_tw_all<<<Bq*Lq + Bp*Lp, 128>>>(q_hidden, p_hidden, sparse_w, sparse_b,
                                       p_qh, p_ph, p_tw_q, p_tw_p);
    f2bf_kernel<<<(Hd*Hd/4 + 255)/256, 256>>>(colbert_w, p_w, Hd*Hd/4);
    cudaEventRecord(evA, 0);

    /* main stream: persistent fused GEMM (proj + maxsim via device work queue) */
    fused_gemm<<<304, 128, SMEM_TOTAL>>>(
        pm_aq, pm_ap, pm_w, pm_q, pm_p,
        p_Qcb, p_Pcb, p_ssq_q, p_ssq_p, colbert_b, q_mask, p_mask, p_qmax);

    /* side stream: independent small kernels (forked after evA so they are captured) */
    cudaStreamWaitEvent(s2, evA, 0);
    dense_kernel<<<gQP, 256, 0, s2>>>(q_hidden, p_hidden, out);
    canon_kernel<<<Bq, Lq, 0, s2>>>(q_ids, p_tw_q, p_wq, Lq);
    canon_kernel<<<Bp, Lp, 0, s2>>>(p_ids, p_tw_p, p_wp, Lp);
    sparse_score_kernel<<<gQP, 256, 0, s2>>>(q_ids, p_wq, p_ids, p_wp, out);
    cudaEventRecord(evB, s2);

    /* join + final */
    cudaStreamWaitEvent(0, evB, 0);
    colbert_final_kernel<<<gQP, 128>>>(p_qmax, p_ssq_q, q_mask, out);
}

// round 15
// speedup vs baseline: 1.1324x; 1.1324x over previous
#include <cuda_runtime.h>
#include <cuda.h>
#include <cuda_bf16.h>
#include <math.h>
#include <stdint.h>
#include <dlfcn.h>

#define Bq 8
#define Lq 128
#define Bp 64
#define Lp 512
#define Hd 1024
#define MQ (Bq*(Lq-1))   /* 1016  */
#define MP (Bp*(Lp-1))   /* 32704 */
#define QTILES 8
#define PTILES 256
#define INV_TEMP 50.0f

/* GEMM: block 128x128, 4 warps (2Mx2N), warp tile 64x64, K-stage 64,
   3-stage ring fed by one 2D TMA tile load per operand per stage.
   Producer/consumer mbarrier pairs: FB (tx-complete) + EB (128-arrive). */
#define KS   64
#define NSTG (Hd/KS)          /* 16 */
#define ROWB 128              /* SW128-swizzled rows */
#define TILEB (128*ROWB)      /* 16384 B */
#define STGB  (2*TILEB)       /* 32768 B */
#define NPIPE 3
#define RED_OFF  (NPIPE*STGB)      /* 98304 */
#define RSQP_OFF (RED_OFF + 1024)
#define MBAR_OFF (RSQP_OFF + 512)  /* FB0,FB1,FB2,EB0,EB1,EB2 (8B each) */
#define SMEM_TOTAL (MBAR_OFF + 64) /* ~99.9 KB -> 2 CTA/SM */

/* ---------------- scratch (allocation-free: device globals) ---------------- */
__device__ float g_tw_q[Bq*Lq];
__device__ float g_wq[Bq*Lq];
__device__ float g_tw_p[Bp*Lp];
__device__ float g_wp[Bp*Lp];
__device__ float g_qmax[(size_t)MQ*Bp*4];
__device__ float g_ssq_q[MQ*16];
__device__ float g_ssq_p[(size_t)MP*16];
__device__ __align__(256) __nv_bfloat16 g_qh_bf[(size_t)MQ*Hd];   /* compact, CLS dropped */
__device__ __align__(256) __nv_bfloat16 g_ph_bf[(size_t)MP*Hd];   /* compact, CLS dropped */
__device__ __align__(256) __nv_bfloat16 g_w_bf[(size_t)Hd*Hd];
__device__ __align__(256) __nv_bfloat16 g_Qcb[(size_t)MQ*Hd];
__device__ __align__(256) __nv_bfloat16 g_Pcb[(size_t)MP*Hd];
__device__ __align__(128) CUtensorMap g_map_aq, g_map_ap, g_map_w, g_map_q, g_map_p;

/* ---------------- helpers ---------------- */
__device__ __forceinline__ uint32_t sw128(uint32_t o){ return o ^ ((o>>3)&0x70u); }

__device__ __forceinline__ void mma_bf16(float* c, const unsigned* a, const unsigned* b){
    asm volatile("mma.sync.aligned.m16n8k16.row.col.f32.bf16.bf16.f32 "
        "{%0,%1,%2,%3}, {%4,%5,%6,%7}, {%8,%9}, {%0,%1,%2,%3};"
        : "+f"(c[0]), "+f"(c[1]), "+f"(c[2]), "+f"(c[3])
        : "r"(a[0]), "r"(a[1]), "r"(a[2]), "r"(a[3]), "r"(b[0]), "r"(b[1]));
}
__device__ __forceinline__ void ldm_x4(unsigned& r0, unsigned& r1, unsigned& r2, unsigned& r3, unsigned addr){
    asm volatile("ldmatrix.sync.aligned.m8n8.x4.shared.b16 {%0,%1,%2,%3}, [%4];"
        : "=r"(r0), "=r"(r1), "=r"(r2), "=r"(r3) : "r"(addr));
}
__device__ __forceinline__ void tma2d(unsigned dst, const CUtensorMap* map, int x, int y, unsigned mbar){
    asm volatile("cp.async.bulk.tensor.2d.shared::cluster.global.tile.mbarrier::complete_tx::bytes "
                 "[%0], [%1, {%2, %3}], [%4];"
                 :: "r"(dst), "l"(map), "r"(x), "r"(y), "r"(mbar) : "memory");
}
#define TMA_PREFETCH(map) asm volatile("prefetch.tensormap [%0];" :: "l"(map))
#define MBARRIER_INIT(addr, cnt) \
    asm volatile("mbarrier.init.shared.b64 [%0], %1;" :: "r"(addr), "r"(cnt) : "memory")
#define MBARRIER_EXPECT_TX(addr, bytes) \
    asm volatile("mbarrier.arrive.expect_tx.shared.b64 _, [%0], %1;" :: "r"(addr), "r"(bytes) : "memory")
#define MBARRIER_ARRIVE(addr) \
    asm volatile("mbarrier.arrive.shared.b64 _, [%0];" :: "r"(addr) : "memory")
#define MB_WAIT(mbar, parity) do{                                                   \
    uint32_t _done;                                                                 \
    asm volatile("{\n\t.reg .pred p;\n\t"                                           \
        "mbarrier.try_wait.parity.acquire.cta.shared::cta.b64 p, [%1], %2;\n\t"     \
        "selp.b32 %0, 1, 0, p;\n\t}" : "=r"(_done) : "r"(mbar), "r"(parity) : "memory"); \
    while(!_done){                                                                  \
        asm volatile("{\n\t.reg .pred p;\n\t"                                       \
            "mbarrier.try_wait.parity.acquire.cta.shared::cta.b64 p, [%1], %2, 0x989680;\n\t" \
            "selp.b32 %0, 1, 0, p;\n\t}" : "=r"(_done) : "r"(mbar), "r"(parity) : "memory"); \
    }                                                                               \
}while(0)

/* K=64 stage for warp tile 64x64, SW128-swizzled smem: 8 ldsm.x4 -> 32 mma per k-step */
__device__ __forceinline__ void mma_stage64(unsigned abase, unsigned bbase,
                                            int lane, int wm, int wn, float acc[4][8][4])
{
    #pragma unroll
    for (int k=0;k<4;k++){
        int klo = k*16;
        unsigned a[4][4];
        int m_i = lane>>3;
        int arow = ((m_i&1)<<3) + (lane&7);
        int acol = klo + ((m_i>>1)<<3);
        #pragma unroll
        for (int mt=0; mt<4; mt++){
            unsigned addr = abase + sw128((unsigned)((wm*64 + mt*16 + arow)*ROWB + acol*2));
            ldm_x4(a[mt][0], a[mt][1], a[mt][2], a[mt][3], addr);
        }
        unsigned b[4][4];
        int brow = (lane&7) + ((lane>>4)<<3);
        int bcol = klo + (((lane>>3)&1)<<3);
        #pragma unroll
        for (int bpi=0; bpi<4; bpi++){
            unsigned addr = bbase + sw128((unsigned)((wn*64 + bpi*16 + brow)*ROWB + bcol*2));
            ldm_x4(b[bpi][0], b[bpi][1], b[bpi][2], b[bpi][3], addr);
        }
        #pragma unroll
        for (int mt=0; mt<4; mt++)
            #pragma unroll
            for (int nt=0; nt<8; nt++)
                mma_bf16(acc[mt][nt], a[mt], &b[nt>>1][(nt&1)*2]);
    }
}

/* ---------------- merged Q+P projection GEMM (TMA-fed), fused bias/mask epilogue ---------------- */
__global__ void __launch_bounds__(128,2)
proj_mma(const CUtensorMap* __restrict__ mapAq, const CUtensorMap* __restrict__ mapAp,
         const CUtensorMap* __restrict__ mapW,
         __nv_bfloat16* __restrict__ Cq, __nv_bfloat16* __restrict__ Cp,
         float* __restrict__ ssq_q, float* __restrict__ ssq_p,
         const float* __restrict__ bias,
         const float* __restrict__ maskq, const float* __restrict__ maskp)
{
    extern __shared__ __align__(1024) char smem[];
    unsigned sb = (unsigned)__cvta_generic_to_shared(smem);
    int tid = threadIdx.x, lane = tid&31, wid = tid>>5;
    int wm = wid>>1, wn = wid&1;

    bool isQ = blockIdx.y < QTILES;
    const CUtensorMap* mapA = isQ ? mapAq : mapAp;
    __nv_bfloat16* Cb = isQ ? Cq : Cp;
    float* ssq = isQ ? ssq_q : ssq_p;
    const float* mask = isQ ? maskq : maskp;
    int M  = isQ ? MQ : MP;
    int La = isQ ? Lq : Lp;
    int blkM = (isQ ? blockIdx.y : blockIdx.y - QTILES) * 128;
    int blkN = blockIdx.x*128;
    int Lm1 = La - 1;

    if (tid==0){
        TMA_PREFETCH(mapA);
        TMA_PREFETCH(mapW);
        MBARRIER_INIT(sb+MBAR_OFF,    1u);   /* FB0 */
        MBARRIER_INIT(sb+MBAR_OFF+8,  1u);   /* FB1 */
        MBARRIER_INIT(sb+MBAR_OFF+16, 1u);   /* FB2 */
        MBARRIER_INIT(sb+MBAR_OFF+24, 128u); /* EB0 */
        MBARRIER_INIT(sb+MBAR_OFF+32, 128u); /* EB1 */
        MBARRIER_INIT(sb+MBAR_OFF+40, 128u); /* EB2 */
    }
    __syncthreads();

    #define PROJ_ISSUE(bufi, stg) do{                                       \
        unsigned st_ = sb + (unsigned)(bufi)*STGB;                          \
        unsigned mb_ = sb + MBAR_OFF + (unsigned)(bufi)*8;                  \
        int k0_ = (stg)*KS;                                                 \
        MBARRIER_EXPECT_TX(mb_, (unsigned)STGB);                            \
        tma2d(st_,         mapA, k0_, blkM, mb_);                           \
        tma2d(st_ + TILEB, mapW, k0_, blkN, mb_);                           \
    }while(0)

    float acc[4][8][4];
    #pragma unroll
    for (int mt=0;mt<4;mt++) for (int nt=0;nt<8;nt++) for (int j=0;j<4;j++) acc[mt][nt][j]=0.f;

    if (tid==0){ PROJ_ISSUE(0, 0); PROJ_ISSUE(1, 1); }

    int eph0=0, eph1=0, eph2=0;
    #pragma unroll 1
    for (int s=0; s<NSTG; s++){
        if (s+2 < NSTG && tid==0){
            int b = (s+2)%NPIPE;
            if (s > 0){   /* buffer b was consumed in stage s-1; wait all 128 arrivals */
                if (b==0){ MB_WAIT(sb+MBAR_OFF+24, eph0); eph0^=1; }
                else if (b==1){ MB_WAIT(sb+MBAR_OFF+32, eph1); eph1^=1; }
                else { MB_WAIT(sb+MBAR_OFF+40, eph2); eph2^=1; }
            }
            PROJ_ISSUE(b, s+2);
        }
        int cbuf = s%NPIPE;
        int fph = (s/NPIPE)&1;
        MB_WAIT(sb + MBAR_OFF + (unsigned)cbuf*8, fph);
        unsigned cs = sb + (unsigned)cbuf*STGB;
        mma_stage64(cs, cs + TILEB, lane, wm, wn, acc);
        MBARRIER_ARRIVE(sb + MBAR_OFF + 24 + (unsigned)cbuf*8);
    }
    #undef PROJ_ISSUE

    /* epilogue: bias + mask, partial sumsq, bf16 store (unnormalized) */
    #pragma unroll
    for (int mt=0;mt<4;mt++){
        #pragma unroll
        for (int half=0; half<2; half++){
            int gr = blkM + wm*64 + mt*16 + (lane>>2) + half*8;
            bool valid = gr < M;
            float m = 0.f;
            if (valid) m = mask[(gr/Lm1)*La + gr%Lm1 + 1];
            float ss = 0.f;
            #pragma unroll
            for (int nt=0;nt<8;nt++){
                int gc = blkN + wn*64 + nt*8 + 2*(lane&3);
                float2 bv2 = *(const float2*)(bias + gc);
                float v0 = (acc[mt][nt][half*2+0] + bv2.x) * m;
                float v1 = (acc[mt][nt][half*2+1] + bv2.y) * m;
                ss = fmaf(v0,v0, fmaf(v1,v1, ss));
                if (valid){
                    __nv_bfloat162 bv = __floats2bfloat162_rn(v0, v1);
                    *(__nv_bfloat162*)(Cb + (size_t)gr*Hd + gc) = bv;
                }
            }
            ss += __shfl_xor_sync(0xffffffffu, ss, 1);
            ss += __shfl_xor_sync(0xffffffffu, ss, 2);
            if (valid && (lane&3)==0)
                ssq[(size_t)gr*16 + blockIdx.x*2 + wn] = ss;
        }
    }
}

/* ---------------- maxsim GEMM (quarter-split, TMA-fed) with fused p-norm scaling ---------------- */
__global__ void __launch_bounds__(128,2)
maxsim_mma(const CUtensorMap* __restrict__ mapQ, const CUtensorMap* __restrict__ mapP,
           const float* __restrict__ ssq_p, float* __restrict__ qmax4)
{
    extern __shared__ __align__(1024) char smem[];
    unsigned sb = (unsigned)__cvta_generic_to_shared(smem);
    float* red  = (float*)(smem + RED_OFF);
    float* rsqs = (float*)(smem + RSQP_OFF);
    int tid = threadIdx.x, lane = tid&31, wid = tid>>5;
    int wm = wid>>1, wn = wid&1;
    int pbi = blockIdx.x>>2, qc = blockIdx.x&3;
    int blkM = blockIdx.y*128;
    int brow0 = pbi*(Lp-1) + qc*128;

    int bvv = (Lp-1) - qc*128; if (bvv > 128) bvv = 128;

    if (tid==0){
        TMA_PREFETCH(mapQ);
        TMA_PREFETCH(mapP);
        MBARRIER_INIT(sb+MBAR_OFF,    1u);
        MBARRIER_INIT(sb+MBAR_OFF+8,  1u);
        MBARRIER_INIT(sb+MBAR_OFF+16, 1u);
        MBARRIER_INIT(sb+MBAR_OFF+24, 128u);
        MBARRIER_INIT(sb+MBAR_OFF+32, 128u);
        MBARRIER_INIT(sb+MBAR_OFF+40, 128u);
    }
    /* per-passage-token reciprocal norms into smem (overlaps pipeline fill) */
    if (tid < bvv){
        const float4* sp = (const float4*)(ssq_p + ((long)brow0 + tid)*16);
        float4 a0 = sp[0], a1 = sp[1], a2 = sp[2], a3 = sp[3];
        float t = ((a0.x+a0.y)+(a0.z+a0.w)) + ((a1.x+a1.y)+(a1.z+a1.w))
                + ((a2.x+a2.y)+(a2.z+a2.w)) + ((a3.x+a3.y)+(a3.z+a3.w));
        rsqs[tid] = 1.0f / fmaxf(sqrtf(t), 1e-12f);
    }
    __syncthreads();

    #define MS_ISSUE(bufi, stg) do{                                         \
        unsigned st_ = sb + (unsigned)(bufi)*STGB;                          \
        unsigned mb_ = sb + MBAR_OFF + (unsigned)(bufi)*8;                  \
        int k0_ = (stg)*KS;                                                 \
        MBARRIER_EXPECT_TX(mb_, (unsigned)STGB);                            \
        tma2d(st_,         mapQ, k0_, blkM,  mb_);                          \
        tma2d(st_ + TILEB, mapP, k0_, brow0, mb_);                          \
    }while(0)

    float acc[4][8][4];
    #pragma unroll
    for (int mt=0;mt<4;mt++) for (int nt=0;nt<8;nt++) for (int j=0;j<4;j++) acc[mt][nt][j]=0.f;

    if (tid==0){ MS_ISSUE(0, 0); MS_ISSUE(1, 1); }

    int eph0=0, eph1=0, eph2=0;
    #pragma unroll 1
    for (int s=0; s<NSTG; s++){
        if (s+2 < NSTG && tid==0){
            int b = (s+2)%NPIPE;
            if (s > 0){
                if (b==0){ MB_WAIT(sb+MBAR_OFF+24, eph0); eph0^=1; }
                else if (b==1){ MB_WAIT(sb+MBAR_OFF+32, eph1); eph1^=1; }
                else { MB_WAIT(sb+MBAR_OFF+40, eph2); eph2^=1; }
            }
            MS_ISSUE(b, s+2);
        }
        int cbuf = s%NPIPE;
        int fph = (s/NPIPE)&1;
        MB_WAIT(sb + MBAR_OFF + (unsigned)cbuf*8, fph);
        unsigned cs = sb + (unsigned)cbuf*STGB;
        mma_stage64(cs, cs + TILEB, lane, wm, wn, acc);
        MBARRIER_ARRIVE(sb + MBAR_OFF + 24 + (unsigned)cbuf*8);
    }
    #undef MS_ISSUE

    /* fold: apply per-token reciprocal norm, then running max */
    float runmax[4][2];
    #pragma unroll
    for (int mt=0;mt<4;mt++){ runmax[mt][0]=-1e30f; runmax[mt][1]=-1e30f; }
    #pragma unroll
    for (int nt=0;nt<8;nt++){
        int c0 = wn*64 + nt*8 + 2*(lane&3);
        bool v0 = c0     < bvv;
        bool v1 = c0 + 1 < bvv;
        float sp0 = v0 ? rsqs[c0]   : 0.f;
        float sp1 = v1 ? rsqs[c0+1] : 0.f;
        #pragma unroll
        for (int mt=0;mt<4;mt++){
            if (v0){
                runmax[mt][0] = fmaxf(runmax[mt][0], acc[mt][nt][0]*sp0);
                runmax[mt][1] = fmaxf(runmax[mt][1], acc[mt][nt][2]*sp0);
            }
            if (v1){
                runmax[mt][0] = fmaxf(runmax[mt][0], acc[mt][nt][1]*sp1);
                runmax[mt][1] = fmaxf(runmax[mt][1], acc[mt][nt][3]*sp1);
            }
        }
    }

    #pragma unroll
    for (int mt=0;mt<4;mt++){
        #pragma unroll
        for (int h=0;h<2;h++){
            runmax[mt][h] = fmaxf(runmax[mt][h], __shfl_xor_sync(0xffffffffu, runmax[mt][h], 1));
            runmax[mt][h] = fmaxf(runmax[mt][h], __shfl_xor_sync(0xffffffffu, runmax[mt][h], 2));
        }
    }
    if ((lane&3)==0){
        #pragma unroll
        for (int mt=0;mt<4;mt++){
            int row = wm*64 + mt*16 + (lane>>2);
            red[row*2 + wn]     = runmax[mt][0];
            red[(row+8)*2 + wn] = runmax[mt][1];
        }
    }
    __syncthreads();
    {
        int gr = blkM + tid;
        if (gr < MQ)
            qmax4[(size_t)gr*(Bp*4) + blockIdx.x] = fmaxf(red[tid*2], red[tid*2+1]);
    }
}

/* ---------------- merged f32->bf16 convert (compact, CLS-dropped) + sparse token weight ---------------- */
__global__ void cvt_tw_all(const float* __restrict__ qh, const float* __restrict__ ph,
                           const float* __restrict__ sw, const float* __restrict__ sbp,
                           __nv_bfloat16* __restrict__ qbf, __nv_bfloat16* __restrict__ pbf,
                           float* __restrict__ twq, float* __restrict__ twp)
{
    int row = blockIdx.x, tid = threadIdx.x;
    int lane = tid&31, wid = tid>>5;
    const float* h; __nv_bfloat16* o; float* tw; int r, L;
    if (row < Bq*Lq){ h = qh; o = qbf; tw = twq; r = row; L = Lq; }
    else            { r = row - Bq*Lq; h = ph; o = pbf; tw = twp; L = Lp; }
    int b = r / L, t = r % L;
    const float* hp = h + (size_t)r*Hd + tid*8;
    float4 a = *(const float4*)hp;
    float4 bb = *(const float4*)(hp+4);
    const float* w = sw + tid*8;
    float4 wa = *(const float4*)w;
    float4 wb = *(const float4*)(w+4);
    if (t > 0){
        int cr = b*(L-1) + (t-1);
        uint4 ov;
        __nv_bfloat162 p0 = __floats2bfloat162_rn(a.x, a.y);
        __nv_bfloat162 p1 = __floats2bfloat162_rn(a.z, a.w);
        __nv_bfloat162 p2 = __floats2bfloat162_rn(bb.x, bb.y);
        __nv_bfloat162 p3 = __floats2bfloat162_rn(bb.z, bb.w);
        ov.x = *(unsigned*)&p0; ov.y = *(unsigned*)&p1; ov.z = *(unsigned*)&p2; ov.w = *(unsigned*)&p3;
        *(uint4*)(o + (size_t)cr*Hd + tid*8) = ov;
    }
    float s = fmaf(a.x,wa.x, fmaf(a.y,wa.y, fmaf(a.z,wa.z, fmaf(a.w,wa.w,
              fmaf(bb.x,wb.x, fmaf(bb.y,wb.y, fmaf(bb.z,wb.z, bb.w*wb.w)))))));
    #pragma unroll
    for (int of=16;of;of>>=1) s += __shfl_xor_sync(0xffffffffu, s, of);
    __shared__ float ws[4];
    if (lane==0) ws[wid] = s;
    __syncthreads();
    if (tid==0) tw[r] = fmaxf(ws[0]+ws[1]+ws[2]+ws[3] + sbp[0], 0.f);
}

/* ---------------- f32 -> bf16 convert (weights only) ---------------- */
__global__ void f2bf_kernel(const float* __restrict__ in, __nv_bfloat16* __restrict__ out, int n4){
    int i = blockIdx.x*blockDim.x + threadIdx.x;
    if (i < n4){
        float4 v = *(const float4*)(in + (size_t)i*4);
        __nv_bfloat162 lo = __floats2bfloat162_rn(v.x, v.y);
        __nv_bfloat162 hi = __floats2bfloat162_rn(v.z, v.w);
        uint2 o; o.x = *(unsigned*)&lo; o.y = *(unsigned*)&hi;
        *(uint2*)(out + (size_t)i*4) = o;
    }
}

/* ---------------- dense: CLS cosine / TEMP ---------------- */
__global__ void dense_kernel(const float* __restrict__ qh, const float* __restrict__ ph,
                             float* __restrict__ out)
{
    int pb = blockIdx.x, qb = blockIdx.y, tid = threadIdx.x;
    const float* q = qh + (size_t)qb*Lq*Hd;
    const float* p = ph + (size_t)pb*Lp*Hd;
    float qq=0.f, pp=0.f, qp=0.f;
    for (int i=tid;i<Hd;i+=256){ float a=q[i], b=p[i];
        qq=fmaf(a,a,qq); pp=fmaf(b,b,pp); qp=fmaf(a,b,qp); }
    __shared__ float r0[256], r1[256], r2[256];
    r0[tid]=qq; r1[tid]=pp; r2[tid]=qp; __syncthreads();
    for (int o=128;o>0;o>>=1){
        if (tid<o){ r0[tid]+=r0[tid+o]; r1[tid]+=r1[tid+o]; r2[tid]+=r2[tid+o]; }
        __syncthreads();
    }
    if (tid==0){
        float d = fmaxf(sqrtf(r0[0]),1e-12f)*fmaxf(sqrtf(r1[0]),1e-12f);
        out[qb*Bp+pb] = r2[0]/d*INV_TEMP;
    }
}

/* ---------------- sparse dedup + scoring ---------------- */
__global__ void canon_kernel(const int* __restrict__ ids, const float* __restrict__ tw,
                             float* __restrict__ weff, int L)
{
    __shared__ int   sid[512];
    __shared__ float stw[512];
    int b = blockIdx.x, i = threadIdx.x;
    int base = b*L;
    sid[i] = ids[base+i]; stw[i] = tw[base+i];
    __syncthreads();
    float w = stw[i]; int id = sid[i];
    if (id < 4) w = 0.f;
    else {
        for (int j=0;j<L;j++){
            if (j!=i && sid[j]==id){
                float wj = stw[j];
                if (wj > w || (wj==w && j<i)) { w=0.f; break; }
            }
        }
    }
    weff[base+i] = w;
}

__global__ void sparse_score_kernel(const int* __restrict__ q_ids, const float* __restrict__ wq,
                                    const int* __restrict__ p_ids, const float* __restrict__ wp,
                                    float* __restrict__ out)
{
    __shared__ int   spid[Lp];
    __shared__ float spw[Lp];
    __shared__ float red[256];
    int pb=blockIdx.x, qb=blockIdx.y, tid=threadIdx.x;
    for (int j=tid;j<Lp;j+=256){ spid[j]=p_ids[pb*Lp+j]; spw[j]=wp[pb*Lp+j]; }
    __syncthreads();
    float s = 0.f;
    if (tid < Lq){
        int id = q_ids[qb*Lq+tid]; float w = wq[qb*Lq+tid];
        if (w > 0.f){
            for (int j=0;j<Lp;j++) if (spid[j]==id) s = fmaf(w, spw[j], s);
        }
    }
    red[tid]=s; __syncthreads();
    for (int o=128;o>0;o>>=1){ if (tid<o) red[tid]+=red[tid+o]; __syncthreads(); }
    if (tid==0) out[Bq*Bp + qb*Bp+pb] = red[0]*INV_TEMP;
}

__global__ void colbert_final_kernel(const float* __restrict__ qmax4,
                                     const float* __restrict__ ssq_q,
                                     const float* __restrict__ q_mask,
                                     float* __restrict__ out)
{
    int pb=blockIdx.x, qb=blockIdx.y, tid=threadIdx.x;  /* 128 threads */
    float v=0.f, mm=0.f;
    if (tid < Lq-1){
        int gr = qb*(Lq-1)+tid;
        const float* qm = qmax4 + (size_t)gr*(Bp*4) + pb*4;
        float m4 = fmaxf(fmaxf(qm[0],qm[1]), fmaxf(qm[2],qm[3]));
        const float4* sp = (const float4*)(ssq_q + gr*16);
        float4 a0 = sp[0], a1 = sp[1], a2 = sp[2], a3 = sp[3];
        float t = ((a0.x+a0.y)+(a0.z+a0.w)) + ((a1.x+a1.y)+(a1.z+a1.w))
                + ((a2.x+a2.y)+(a2.z+a2.w)) + ((a3.x+a3.y)+(a3.z+a3.w));
        v  = m4 / fmaxf(sqrtf(t), 1e-12f);
        mm = q_mask[qb*Lq + tid + 1];
    }
    __shared__ float rv[128], rm[128];
    rv[tid]=v; rm[tid]=mm; __syncthreads();
    for (int o=64;o>0;o>>=1){ if (tid<o){ rv[tid]+=rv[tid+o]; rm[tid]+=rm[tid+o]; } __syncthreads(); }
    if (tid==0) out[2*Bq*Bp + qb*Bp+pb] = rv[0]/rm[0]*INV_TEMP;
}

/* ---------------- host: tensor-map creation via dlopen'd driver API ---------------- */
typedef CUresult (*EncFn)(CUtensorMap*, CUtensorMapDataType, cuuint32_t, void*,
                          const cuuint64_t*, const cuuint64_t*, const cuuint32_t*,
                          const cuuint32_t*, CUtensorMapInterleave, CUtensorMapSwizzle,
                          CUtensorMapL2promotion, CUtensorMapFloatOOBfill);

static void make_map2d(EncFn enc, CUtensorMap* m, void* addr, unsigned long long d0, unsigned long long d1){
    cuuint64_t dims[2]    = {(cuuint64_t)d0, (cuuint64_t)d1};
    cuuint64_t strides[1] = {(cuuint64_t)(d0*2)};
    cuuint32_t box[2]     = {(cuuint32_t)KS, 128u};
    cuuint32_t es[2]      = {1u, 1u};
    enc(m, CU_TENSOR_MAP_DATA_TYPE_BFLOAT16, 2, addr, dims, strides, box, es,
        CU_TENSOR_MAP_INTERLEAVE_NONE, CU_TENSOR_MAP_SWIZZLE_128B,
        CU_TENSOR_MAP_L2_PROMOTION_L2_128B, CU_TENSOR_MAP_FLOAT_OOB_FILL_NONE);
}

/* ---------------- launcher ---------------- */
extern "C" void kernel_launch(void* const* d_in, const int* in_sizes, int n_in,
                              void* d_out, int out_size)
{
    const float* q_hidden  = (const float*)d_in[0];
    const float* p_hidden  = (const float*)d_in[1];
    const float* q_mask    = (const float*)d_in[2];
    const float* p_mask    = (const float*)d_in[3];
    const int*   q_ids     = (const int*)  d_in[4];
    const int*   p_ids     = (const int*)  d_in[5];
    const float* colbert_w = (const float*)d_in[6];
    const float* colbert_b = (const float*)d_in[7];
    const float* sparse_w  = (const float*)d_in[8];
    const float* sparse_b  = (const float*)d_in[9];
    float* out = (float*)d_out;

    static float *p_tw_q=nullptr,*p_wq=nullptr,*p_tw_p=nullptr,*p_wp=nullptr,
                 *p_qmax=nullptr,*p_ssq_q=nullptr,*p_ssq_p=nullptr;
    static __nv_bfloat16 *p_qh=nullptr,*p_ph=nullptr,*p_w=nullptr,*p_Qcb=nullptr,*p_Pcb=nullptr;
    static CUtensorMap *pm_aq=nullptr,*pm_ap=nullptr,*pm_w=nullptr,*pm_q=nullptr,*pm_p=nullptr;
    static cudaStream_t s2 = nullptr;
    static cudaEvent_t evA = nullptr, evB = nullptr;
    if (!p_tw_q){
        cudaGetSymbolAddress((void**)&p_tw_q, g_tw_q);
        cudaGetSymbolAddress((void**)&p_wq,   g_wq);
        cudaGetSymbolAddress((void**)&p_tw_p, g_tw_p);
        cudaGetSymbolAddress((void**)&p_wp,   g_wp);
        cudaGetSymbolAddress((void**)&p_qmax, g_qmax);
        cudaGetSymbolAddress((void**)&p_ssq_q, g_ssq_q);
        cudaGetSymbolAddress((void**)&p_ssq_p, g_ssq_p);
        cudaGetSymbolAddress((void**)&p_qh,   g_qh_bf);
        cudaGetSymbolAddress((void**)&p_ph,   g_ph_bf);
        cudaGetSymbolAddress((void**)&p_w,    g_w_bf);
        cudaGetSymbolAddress((void**)&p_Qcb,  g_Qcb);
        cudaGetSymbolAddress((void**)&p_Pcb,  g_Pcb);
        cudaGetSymbolAddress((void**)&pm_aq,  g_map_aq);
        cudaGetSymbolAddress((void**)&pm_ap,  g_map_ap);
        cudaGetSymbolAddress((void**)&pm_w,   g_map_w);
        cudaGetSymbolAddress((void**)&pm_q,   g_map_q);
        cudaGetSymbolAddress((void**)&pm_p,   g_map_p);
        cudaFuncSetAttribute(proj_mma,   cudaFuncAttributeMaxDynamicSharedMemorySize, SMEM_TOTAL);
        cudaFuncSetAttribute(maxsim_mma, cudaFuncAttributeMaxDynamicSharedMemorySize, SMEM_TOTAL);
        cudaStreamCreateWithFlags(&s2, cudaStreamNonBlocking);
        cudaEventCreateWithFlags(&evA, cudaEventDisableTiming);
        cudaEventCreateWithFlags(&evB, cudaEventDisableTiming);

        /* build tensor maps once (first, uncaptured call) */
        void* h = dlopen("libcuda.so.1", RTLD_NOW | RTLD_GLOBAL);
        if (!h) h = dlopen("libcuda.so", RTLD_NOW | RTLD_GLOBAL);
        EncFn enc = (EncFn)dlsym(h, "cuTensorMapEncodeTiled");
        CUtensorMap hm_aq, hm_ap, hm_w, hm_q, hm_p;
        make_map2d(enc, &hm_aq, p_qh,  Hd, MQ);
        make_map2d(enc, &hm_ap, p_ph,  Hd, MP);
        make_map2d(enc, &hm_w,  p_w,   Hd, Hd);
        make_map2d(enc, &hm_q,  p_Qcb, Hd, MQ);
        make_map2d(enc, &hm_p,  p_Pcb, Hd, MP);
        cudaMemcpyToSymbol(g_map_aq, &hm_aq, sizeof(CUtensorMap));
        cudaMemcpyToSymbol(g_map_ap, &hm_ap, sizeof(CUtensorMap));
        cudaMemcpyToSymbol(g_map_w,  &hm_w,  sizeof(CUtensorMap));
        cudaMemcpyToSymbol(g_map_q,  &hm_q,  sizeof(CUtensorMap));
        cudaMemcpyToSymbol(g_map_p,  &hm_p,  sizeof(CUtensorMap));
    }

    dim3 gQP(Bp, Bq);

    /* main stream: converts (+ fused sparse token weights, compact bf16 layout) */
    cvt_tw_all<<<Bq*Lq + Bp*Lp, 128>>>(q_hidden, p_hidden, sparse_w, sparse_b,
                                       p_qh, p_ph, p_tw_q, p_tw_p);
    f2bf_kernel<<<(Hd*Hd/4 + 255)/256, 256>>>(colbert_w, p_w, Hd*Hd/4);
    cudaEventRecord(evA, 0);

    /* main stream: GEMM chain */
    proj_mma<<<dim3(Hd/128, QTILES+PTILES), 128, SMEM_TOTAL>>>(
        pm_aq, pm_ap, pm_w, p_Qcb, p_Pcb, p_ssq_q, p_ssq_p, colbert_b, q_mask, p_mask);
    maxsim_mma<<<dim3(Bp*4, QTILES), 128, SMEM_TOTAL>>>(pm_q, pm_p, p_ssq_p, p_qmax);

    /* side stream: independent small kernels (forked AFTER evA so they are captured) */
    cudaStreamWaitEvent(s2, evA, 0);
    dense_kernel<<<gQP, 256, 0, s2>>>(q_hidden, p_hidden, out);
    canon_kernel<<<Bq, Lq, 0, s2>>>(q_ids, p_tw_q, p_wq, Lq);
    canon_kernel<<<Bp, Lp, 0, s2>>>(p_ids, p_tw_p, p_wp, Lp);
    sparse_score_kernel<<<gQP, 256, 0, s2>>>(q_ids, p_wq, p_ids, p_wp, out);
    cudaEventRecord(evB, s2);

    /* join + final */
    cudaStreamWaitEvent(0, evB, 0);
    colbert_final_kernel<<<gQP, 128>>>(p_qmax, p_ssq_q, q_mask, out);
}

// round 16
// speedup vs baseline: 1.1524x; 1.0176x over previous
#include <cuda_runtime.h>
#include <cuda.h>
#include <cuda_bf16.h>
#include <math.h>
#include <stdint.h>
#include <dlfcn.h>

#define Bq 8
#define Lq 128
#define Bp 64
#define Lp 512
#define Hd 1024
#define MQ (Bq*(Lq-1))   /* 1016  */
#define MP (Bp*(Lp-1))   /* 32704 */
#define QTILES 8
#define PTILES 256
#define INV_TEMP 50.0f

/* GEMM: block 128x128, 4 warps (2Mx2N), warp tile 64x64, K-stage 64,
   3-stage ring fed by one 2D TMA tile load per operand per stage.
   Producer/consumer mbarrier pairs: FB (tx-complete) + EB (128-arrive). */
#define KS   64
#define NSTG (Hd/KS)          /* 16 */
#define ROWB 128              /* SW128-swizzled rows */
#define TILEB (128*ROWB)      /* 16384 B */
#define STGB  (2*TILEB)       /* 32768 B */
#define NPIPE 3
#define RED_OFF  (NPIPE*STGB)      /* 98304 */
#define RSQP_OFF (RED_OFF + 1024)
#define MBAR_OFF (RSQP_OFF + 512)  /* FB0,FB1,FB2,EB0,EB1,EB2 (8B each) */
#define SMEM_TOTAL (MBAR_OFF + 64) /* ~99.9 KB -> 2 CTA/SM */

/* ---------------- scratch (allocation-free: device globals) ---------------- */
__device__ float g_tw_q[Bq*Lq];
__device__ float g_wq[Bq*Lq];
__device__ float g_tw_p[Bp*Lp];
__device__ float g_wp[Bp*Lp];
__device__ float g_qmax[(size_t)MQ*Bp*4];
__device__ float g_ssq_q[MQ*16];
__device__ float g_ssq_p[(size_t)MP*16];
__device__ __align__(256) __nv_bfloat16 g_qh_bf[(size_t)MQ*Hd];   /* compact, CLS dropped */
__device__ __align__(256) __nv_bfloat16 g_ph_bf[(size_t)MP*Hd];   /* compact, CLS dropped */
__device__ __align__(256) __nv_bfloat16 g_w_bf[(size_t)Hd*Hd];
__device__ __align__(256) __nv_bfloat16 g_Qcb[(size_t)MQ*Hd];
__device__ __align__(256) __nv_bfloat16 g_Pcb[(size_t)MP*Hd];
__device__ __align__(128) CUtensorMap g_map_aq, g_map_ap, g_map_w, g_map_q, g_map_p;

/* ---------------- helpers ---------------- */
__device__ __forceinline__ uint32_t sw128(uint32_t o){ return o ^ ((o>>3)&0x70u); }

__device__ __forceinline__ void mma_bf16(float* c, const unsigned* a, const unsigned* b){
    asm volatile("mma.sync.aligned.m16n8k16.row.col.f32.bf16.bf16.f32 "
        "{%0,%1,%2,%3}, {%4,%5,%6,%7}, {%8,%9}, {%0,%1,%2,%3};"
        : "+f"(c[0]), "+f"(c[1]), "+f"(c[2]), "+f"(c[3])
        : "r"(a[0]), "r"(a[1]), "r"(a[2]), "r"(a[3]), "r"(b[0]), "r"(b[1]));
}
__device__ __forceinline__ void ldm_x4(unsigned& r0, unsigned& r1, unsigned& r2, unsigned& r3, unsigned addr){
    asm volatile("ldmatrix.sync.aligned.m8n8.x4.shared.b16 {%0,%1,%2,%3}, [%4];"
        : "=r"(r0), "=r"(r1), "=r"(r2), "=r"(r3) : "r"(addr));
}
__device__ __forceinline__ void tma2d(unsigned dst, const CUtensorMap* map, int x, int y, unsigned mbar){
    asm volatile("cp.async.bulk.tensor.2d.shared::cluster.global.tile.mbarrier::complete_tx::bytes "
                 "[%0], [%1, {%2, %3}], [%4];"
                 :: "r"(dst), "l"(map), "r"(x), "r"(y), "r"(mbar) : "memory");
}
#define TMA_PREFETCH(map) asm volatile("prefetch.tensormap [%0];" :: "l"(map))
#define MBARRIER_INIT(addr, cnt) \
    asm volatile("mbarrier.init.shared.b64 [%0], %1;" :: "r"(addr), "r"(cnt) : "memory")
#define MBARRIER_EXPECT_TX(addr, bytes) \
    asm volatile("mbarrier.arrive.expect_tx.shared.b64 _, [%0], %1;" :: "r"(addr), "r"(bytes) : "memory")
#define MBARRIER_ARRIVE(addr) \
    asm volatile("mbarrier.arrive.shared.b64 _, [%0];" :: "r"(addr) : "memory")
#define MB_WAIT(mbar, parity) do{                                                   \
    uint32_t _done;                                                                 \
    asm volatile("{\n\t.reg .pred p;\n\t"                                           \
        "mbarrier.try_wait.parity.acquire.cta.shared::cta.b64 p, [%1], %2;\n\t"     \
        "selp.b32 %0, 1, 0, p;\n\t}" : "=r"(_done) : "r"(mbar), "r"(parity) : "memory"); \
    while(!_done){                                                                  \
        asm volatile("{\n\t.reg .pred p;\n\t"                                       \
            "mbarrier.try_wait.parity.acquire.cta.shared::cta.b64 p, [%1], %2, 0x989680;\n\t" \
            "selp.b32 %0, 1, 0, p;\n\t}" : "=r"(_done) : "r"(mbar), "r"(parity) : "memory"); \
    }                                                                               \
}while(0)
/* relaxed wait: producers only (post-wait accesses are async-proxy TMA) */
#define MB_WAIT_RLX(mbar, parity) do{                                               \
    uint32_t _done;                                                                 \
    asm volatile("{\n\t.reg .pred p;\n\t"                                           \
        "mbarrier.try_wait.parity.relaxed.cta.shared::cta.b64 p, [%1], %2, 0x989680;\n\t" \
        "selp.b32 %0, 1, 0, p;\n\t}" : "=r"(_done) : "r"(mbar), "r"(parity) : "memory"); \
    while(!_done){                                                                  \
        asm volatile("{\n\t.reg .pred p;\n\t"                                       \
            "mbarrier.try_wait.parity.relaxed.cta.shared::cta.b64 p, [%1], %2, 0x989680;\n\t" \
            "selp.b32 %0, 1, 0, p;\n\t}" : "=r"(_done) : "r"(mbar), "r"(parity) : "memory"); \
    }                                                                               \
}while(0)

/* K=64 stage for warp tile 64x64, SW128-swizzled smem: 8 ldsm.x4 -> 32 mma per k-step */
__device__ __forceinline__ void mma_stage64(unsigned abase, unsigned bbase,
                                            int lane, int wm, int wn, float acc[4][8][4])
{
    #pragma unroll
    for (int k=0;k<4;k++){
        int klo = k*16;
        unsigned a[4][4];
        int m_i = lane>>3;
        int arow = ((m_i&1)<<3) + (lane&7);
        int acol = klo + ((m_i>>1)<<3);
        #pragma unroll
        for (int mt=0; mt<4; mt++){
            unsigned addr = abase + sw128((unsigned)((wm*64 + mt*16 + arow)*ROWB + acol*2));
            ldm_x4(a[mt][0], a[mt][1], a[mt][2], a[mt][3], addr);
        }
        unsigned b[4][4];
        int brow = (lane&7) + ((lane>>4)<<3);
        int bcol = klo + (((lane>>3)&1)<<3);
        #pragma unroll
        for (int bpi=0; bpi<4; bpi++){
            unsigned addr = bbase + sw128((unsigned)((wn*64 + bpi*16 + brow)*ROWB + bcol*2));
            ldm_x4(b[bpi][0], b[bpi][1], b[bpi][2], b[bpi][3], addr);
        }
        #pragma unroll
        for (int mt=0; mt<4; mt++)
            #pragma unroll
            for (int nt=0; nt<8; nt++)
                mma_bf16(acc[mt][nt], a[mt], &b[nt>>1][(nt&1)*2]);
    }
}

/* ---------------- merged Q+P projection GEMM (TMA-fed), fused bias/mask epilogue ---------------- */
__global__ void __launch_bounds__(128,2)
proj_mma(const CUtensorMap* __restrict__ mapAq, const CUtensorMap* __restrict__ mapAp,
         const CUtensorMap* __restrict__ mapW,
         __nv_bfloat16* __restrict__ Cq, __nv_bfloat16* __restrict__ Cp,
         float* __restrict__ ssq_q, float* __restrict__ ssq_p,
         const float* __restrict__ bias,
         const float* __restrict__ maskq, const float* __restrict__ maskp)
{
    extern __shared__ __align__(1024) char smem[];
    unsigned sb = (unsigned)__cvta_generic_to_shared(smem);
    int tid = threadIdx.x, lane = tid&31, wid = tid>>5;
    int wm = wid>>1, wn = wid&1;

    bool isQ = blockIdx.y < QTILES;
    const CUtensorMap* mapA = isQ ? mapAq : mapAp;
    __nv_bfloat16* Cb = isQ ? Cq : Cp;
    float* ssq = isQ ? ssq_q : ssq_p;
    const float* mask = isQ ? maskq : maskp;
    int M  = isQ ? MQ : MP;
    int La = isQ ? Lq : Lp;
    int blkM = (isQ ? blockIdx.y : blockIdx.y - QTILES) * 128;
    int blkN = blockIdx.x*128;
    int Lm1 = La - 1;

    if (tid==0){
        TMA_PREFETCH(mapA);
        TMA_PREFETCH(mapW);
        MBARRIER_INIT(sb+MBAR_OFF,    1u);   /* FB0 */
        MBARRIER_INIT(sb+MBAR_OFF+8,  1u);   /* FB1 */
        MBARRIER_INIT(sb+MBAR_OFF+16, 1u);   /* FB2 */
        MBARRIER_INIT(sb+MBAR_OFF+24, 128u); /* EB0 */
        MBARRIER_INIT(sb+MBAR_OFF+32, 128u); /* EB1 */
        MBARRIER_INIT(sb+MBAR_OFF+40, 128u); /* EB2 */
    }
    __syncthreads();

    #define PROJ_ISSUE(bufi, stg) do{                                       \
        unsigned st_ = sb + (unsigned)(bufi)*STGB;                          \
        unsigned mb_ = sb + MBAR_OFF + (unsigned)(bufi)*8;                  \
        int k0_ = (stg)*KS;                                                 \
        MBARRIER_EXPECT_TX(mb_, (unsigned)STGB);                            \
        tma2d(st_,         mapA, k0_, blkM, mb_);                           \
        tma2d(st_ + TILEB, mapW, k0_, blkN, mb_);                           \
    }while(0)

    float acc[4][8][4];
    #pragma unroll
    for (int mt=0;mt<4;mt++) for (int nt=0;nt<8;nt++) for (int j=0;j<4;j++) acc[mt][nt][j]=0.f;

    if (tid==0){ PROJ_ISSUE(0, 0); PROJ_ISSUE(1, 1); }

    int eph0=0, eph1=0, eph2=0;
    #pragma unroll 1
    for (int s=0; s<NSTG; s++){
        if (s+2 < NSTG && tid==0){
            int b = (s+2)%NPIPE;
            if (s > 0){   /* buffer b was consumed in stage s-1; wait all 128 arrivals */
                if (b==0){ MB_WAIT_RLX(sb+MBAR_OFF+24, eph0); eph0^=1; }
                else if (b==1){ MB_WAIT_RLX(sb+MBAR_OFF+32, eph1); eph1^=1; }
                else { MB_WAIT_RLX(sb+MBAR_OFF+40, eph2); eph2^=1; }
            }
            PROJ_ISSUE(b, s+2);
        }
        int cbuf = s%NPIPE;
        int fph = (s/NPIPE)&1;
        MB_WAIT(sb + MBAR_OFF + (unsigned)cbuf*8, fph);
        unsigned cs = sb + (unsigned)cbuf*STGB;
        mma_stage64(cs, cs + TILEB, lane, wm, wn, acc);
        MBARRIER_ARRIVE(sb + MBAR_OFF + 24 + (unsigned)cbuf*8);
    }
    #undef PROJ_ISSUE

    /* epilogue: bias + mask, partial sumsq, bf16 store (unnormalized) */
    #pragma unroll
    for (int mt=0;mt<4;mt++){
        #pragma unroll
        for (int half=0; half<2; half++){
            int gr = blkM + wm*64 + mt*16 + (lane>>2) + half*8;
            bool valid = gr < M;
            float m = 0.f;
            if (valid) m = mask[(gr/Lm1)*La + gr%Lm1 + 1];
            float ss = 0.f;
            #pragma unroll
            for (int nt=0;nt<8;nt++){
                int gc = blkN + wn*64 + nt*8 + 2*(lane&3);
                float2 bv2 = *(const float2*)(bias + gc);
                float v0 = (acc[mt][nt][half*2+0] + bv2.x) * m;
                float v1 = (acc[mt][nt][half*2+1] + bv2.y) * m;
                ss = fmaf(v0,v0, fmaf(v1,v1, ss));
                if (valid){
                    __nv_bfloat162 bv = __floats2bfloat162_rn(v0, v1);
                    *(__nv_bfloat162*)(Cb + (size_t)gr*Hd + gc) = bv;
                }
            }
            ss += __shfl_xor_sync(0xffffffffu, ss, 1);
            ss += __shfl_xor_sync(0xffffffffu, ss, 2);
            if (valid && (lane&3)==0)
                ssq[(size_t)gr*16 + blockIdx.x*2 + wn] = ss;
        }
    }
}

/* ---------------- maxsim GEMM (quarter-split, TMA-fed) with fused p-norm scaling ---------------- */
__global__ void __launch_bounds__(128,2)
maxsim_mma(const CUtensorMap* __restrict__ mapQ, const CUtensorMap* __restrict__ mapP,
           const float* __restrict__ ssq_p, float* __restrict__ qmax4)
{
    extern __shared__ __align__(1024) char smem[];
    unsigned sb = (unsigned)__cvta_generic_to_shared(smem);
    float* red  = (float*)(smem + RED_OFF);
    float* rsqs = (float*)(smem + RSQP_OFF);
    int tid = threadIdx.x, lane = tid&31, wid = tid>>5;
    int wm = wid>>1, wn = wid&1;
    int pbi = blockIdx.x>>2, qc = blockIdx.x&3;
    int blkM = blockIdx.y*128;
    int brow0 = pbi*(Lp-1) + qc*128;

    int bvv = (Lp-1) - qc*128; if (bvv > 128) bvv = 128;

    if (tid==0){
        TMA_PREFETCH(mapQ);
        TMA_PREFETCH(mapP);
        MBARRIER_INIT(sb+MBAR_OFF,    1u);
        MBARRIER_INIT(sb+MBAR_OFF+8,  1u);
        MBARRIER_INIT(sb+MBAR_OFF+16, 1u);
        MBARRIER_INIT(sb+MBAR_OFF+24, 128u);
        MBARRIER_INIT(sb+MBAR_OFF+32, 128u);
        MBARRIER_INIT(sb+MBAR_OFF+40, 128u);
    }
    /* per-passage-token reciprocal norms into smem (overlaps pipeline fill) */
    if (tid < bvv){
        const float4* sp = (const float4*)(ssq_p + ((long)brow0 + tid)*16);
        float4 a0 = sp[0], a1 = sp[1], a2 = sp[2], a3 = sp[3];
        float t = ((a0.x+a0.y)+(a0.z+a0.w)) + ((a1.x+a1.y)+(a1.z+a1.w))
                + ((a2.x+a2.y)+(a2.z+a2.w)) + ((a3.x+a3.y)+(a3.z+a3.w));
        rsqs[tid] = 1.0f / fmaxf(sqrtf(t), 1e-12f);
    }
    __syncthreads();

    #define MS_ISSUE(bufi, stg) do{                                         \
        unsigned st_ = sb + (unsigned)(bufi)*STGB;                          \
        unsigned mb_ = sb + MBAR_OFF + (unsigned)(bufi)*8;                  \
        int k0_ = (stg)*KS;                                                 \
        MBARRIER_EXPECT_TX(mb_, (unsigned)STGB);                            \
        tma2d(st_,         mapQ, k0_, blkM,  mb_);                          \
        tma2d(st_ + TILEB, mapP, k0_, brow0, mb_);                          \
    }while(0)

    float acc[4][8][4];
    #pragma unroll
    for (int mt=0;mt<4;mt++) for (int nt=0;nt<8;nt++) for (int j=0;j<4;j++) acc[mt][nt][j]=0.f;

    if (tid==0){ MS_ISSUE(0, 0); MS_ISSUE(1, 1); }

    int eph0=0, eph1=0, eph2=0;
    #pragma unroll 1
    for (int s=0; s<NSTG; s++){
        if (s+2 < NSTG && tid==0){
            int b = (s+2)%NPIPE;
            if (s > 0){
                if (b==0){ MB_WAIT_RLX(sb+MBAR_OFF+24, eph0); eph0^=1; }
                else if (b==1){ MB_WAIT_RLX(sb+MBAR_OFF+32, eph1); eph1^=1; }
                else { MB_WAIT_RLX(sb+MBAR_OFF+40, eph2); eph2^=1; }
            }
            MS_ISSUE(b, s+2);
        }
        int cbuf = s%NPIPE;
        int fph = (s/NPIPE)&1;
        MB_WAIT(sb + MBAR_OFF + (unsigned)cbuf*8, fph);
        unsigned cs = sb + (unsigned)cbuf*STGB;
        mma_stage64(cs, cs + TILEB, lane, wm, wn, acc);
        MBARRIER_ARRIVE(sb + MBAR_OFF + 24 + (unsigned)cbuf*8);
    }
    #undef MS_ISSUE

    /* fold: apply per-token reciprocal norm, then running max */
    float runmax[4][2];
    #pragma unroll
    for (int mt=0;mt<4;mt++){ runmax[mt][0]=-1e30f; runmax[mt][1]=-1e30f; }
    #pragma unroll
    for (int nt=0;nt<8;nt++){
        int c0 = wn*64 + nt*8 + 2*(lane&3);
        bool v0 = c0     < bvv;
        bool v1 = c0 + 1 < bvv;
        float sp0 = v0 ? rsqs[c0]   : 0.f;
        float sp1 = v1 ? rsqs[c0+1] : 0.f;
        #pragma unroll
        for (int mt=0;mt<4;mt++){
            if (v0){
                runmax[mt][0] = fmaxf(runmax[mt][0], acc[mt][nt][0]*sp0);
                runmax[mt][1] = fmaxf(runmax[mt][1], acc[mt][nt][2]*sp0);
            }
            if (v1){
                runmax[mt][0] = fmaxf(runmax[mt][0], acc[mt][nt][1]*sp1);
                runmax[mt][1] = fmaxf(runmax[mt][1], acc[mt][nt][3]*sp1);
            }
        }
    }

    #pragma unroll
    for (int mt=0;mt<4;mt++){
        #pragma unroll
        for (int h=0;h<2;h++){
            runmax[mt][h] = fmaxf(runmax[mt][h], __shfl_xor_sync(0xffffffffu, runmax[mt][h], 1));
            runmax[mt][h] = fmaxf(runmax[mt][h], __shfl_xor_sync(0xffffffffu, runmax[mt][h], 2));
        }
    }
    if ((lane&3)==0){
        #pragma unroll
        for (int mt=0;mt<4;mt++){
            int row = wm*64 + mt*16 + (lane>>2);
            red[row*2 + wn]     = runmax[mt][0];
            red[(row+8)*2 + wn] = runmax[mt][1];
        }
    }
    __syncthreads();
    {
        int gr = blkM + tid;
        if (gr < MQ)
            qmax4[(size_t)gr*(Bp*4) + blockIdx.x] = fmaxf(red[tid*2], red[tid*2+1]);
    }
}

/* ---------------- merged f32->bf16 convert (compact, CLS-dropped) + sparse token weight ---------------- */
__global__ void cvt_tw_all(const float* __restrict__ qh, const float* __restrict__ ph,
                           const float* __restrict__ sw, const float* __restrict__ sbp,
                           __nv_bfloat16* __restrict__ qbf, __nv_bfloat16* __restrict__ pbf,
                           float* __restrict__ twq, float* __restrict__ twp)
{
    int row = blockIdx.x, tid = threadIdx.x;
    int lane = tid&31, wid = tid>>5;
    const float* h; __nv_bfloat16* o; float* tw; int r, L;
    if (row < Bq*Lq){ h = qh; o = qbf; tw = twq; r = row; L = Lq; }
    else            { r = row - Bq*Lq; h = ph; o = pbf; tw = twp; L = Lp; }
    int b = r / L, t = r % L;
    const float* hp = h + (size_t)r*Hd + tid*8;
    float4 a = *(const float4*)hp;
    float4 bb = *(const float4*)(hp+4);
    const float* w = sw + tid*8;
    float4 wa = *(const float4*)w;
    float4 wb = *(const float4*)(w+4);
    if (t > 0){
        int cr = b*(L-1) + (t-1);
        uint4 ov;
        __nv_bfloat162 p0 = __floats2bfloat162_rn(a.x, a.y);
        __nv_bfloat162 p1 = __floats2bfloat162_rn(a.z, a.w);
        __nv_bfloat162 p2 = __floats2bfloat162_rn(bb.x, bb.y);
        __nv_bfloat162 p3 = __floats2bfloat162_rn(bb.z, bb.w);
        ov.x = *(unsigned*)&p0; ov.y = *(unsigned*)&p1; ov.z = *(unsigned*)&p2; ov.w = *(unsigned*)&p3;
        *(uint4*)(o + (size_t)cr*Hd + tid*8) = ov;
    }
    float s = fmaf(a.x,wa.x, fmaf(a.y,wa.y, fmaf(a.z,wa.z, fmaf(a.w,wa.w,
              fmaf(bb.x,wb.x, fmaf(bb.y,wb.y, fmaf(bb.z,wb.z, bb.w*wb.w)))))));
    #pragma unroll
    for (int of=16;of;of>>=1) s += __shfl_xor_sync(0xffffffffu, s, of);
    __shared__ float ws[4];
    if (lane==0) ws[wid] = s;
    __syncthreads();
    if (tid==0) tw[r] = fmaxf(ws[0]+ws[1]+ws[2]+ws[3] + sbp[0], 0.f);
}

/* ---------------- f32 -> bf16 convert (weights only) ---------------- */
__global__ void f2bf_kernel(const float* __restrict__ in, __nv_bfloat16* __restrict__ out, int n4){
    int i = blockIdx.x*blockDim.x + threadIdx.x;
    if (i < n4){
        float4 v = *(const float4*)(in + (size_t)i*4);
        __nv_bfloat162 lo = __floats2bfloat162_rn(v.x, v.y);
        __nv_bfloat162 hi = __floats2bfloat162_rn(v.z, v.w);
        uint2 o; o.x = *(unsigned*)&lo; o.y = *(unsigned*)&hi;
        *(uint2*)(out + (size_t)i*4) = o;
    }
}

/* ---------------- dense: CLS cosine / TEMP ---------------- */
__global__ void dense_kernel(const float* __restrict__ qh, const float* __restrict__ ph,
                             float* __restrict__ out)
{
    int pb = blockIdx.x, qb = blockIdx.y, tid = threadIdx.x;
    const float* q = qh + (size_t)qb*Lq*Hd;
    const float* p = ph + (size_t)pb*Lp*Hd;
    float qq=0.f, pp=0.f, qp=0.f;
    for (int i=tid;i<Hd;i+=256){ float a=q[i], b=p[i];
        qq=fmaf(a,a,qq); pp=fmaf(b,b,pp); qp=fmaf(a,b,qp); }
    __shared__ float r0[256], r1[256], r2[256];
    r0[tid]=qq; r1[tid]=pp; r2[tid]=qp; __syncthreads();
    for (int o=128;o>0;o>>=1){
        if (tid<o){ r0[tid]+=r0[tid+o]; r1[tid]+=r1[tid+o]; r2[tid]+=r2[tid+o]; }
        __syncthreads();
    }
    if (tid==0){
        float d = fmaxf(sqrtf(r0[0]),1e-12f)*fmaxf(sqrtf(r1[0]),1e-12f);
        out[qb*Bp+pb] = r2[0]/d*INV_TEMP;
    }
}

/* ---------------- sparse dedup + scoring ---------------- */
__global__ void canon_kernel(const int* __restrict__ ids, const float* __restrict__ tw,
                             float* __restrict__ weff, int L)
{
    __shared__ int   sid[512];
    __shared__ float stw[512];
    int b = blockIdx.x, i = threadIdx.x;
    int base = b*L;
    sid[i] = ids[base+i]; stw[i] = tw[base+i];
    __syncthreads();
    float w = stw[i]; int id = sid[i];
    if (id < 4) w = 0.f;
    else {
        for (int j=0;j<L;j++){
            if (j!=i && sid[j]==id){
                float wj = stw[j];
                if (wj > w || (wj==w && j<i)) { w=0.f; break; }
            }
        }
    }
    weff[base+i] = w;
}

__global__ void sparse_score_kernel(const int* __restrict__ q_ids, const float* __restrict__ wq,
                                    const int* __restrict__ p_ids, const float* __restrict__ wp,
                                    float* __restrict__ out)
{
    __shared__ int   spid[Lp];
    __shared__ float spw[Lp];
    __shared__ float red[256];
    int pb=blockIdx.x, qb=blockIdx.y, tid=threadIdx.x;
    for (int j=tid;j<Lp;j+=256){ spid[j]=p_ids[pb*Lp+j]; spw[j]=wp[pb*Lp+j]; }
    __syncthreads();
    float s = 0.f;
    if (tid < Lq){
        int id = q_ids[qb*Lq+tid]; float w = wq[qb*Lq+tid];
        if (w > 0.f){
            for (int j=0;j<Lp;j++) if (spid[j]==id) s = fmaf(w, spw[j], s);
        }
    }
    red[tid]=s; __syncthreads();
    for (int o=128;o>0;o>>=1){ if (tid<o) red[tid]+=red[tid+o]; __syncthreads(); }
    if (tid==0) out[Bq*Bp + qb*Bp+pb] = red[0]*INV_TEMP;
}

__global__ void colbert_final_kernel(const float* __restrict__ qmax4,
                                     const float* __restrict__ ssq_q,
                                     const float* __restrict__ q_mask,
                                     float* __restrict__ out)
{
    int pb=blockIdx.x, qb=blockIdx.y, tid=threadIdx.x;  /* 128 threads */
    float v=0.f, mm=0.f;
    if (tid < Lq-1){
        int gr = qb*(Lq-1)+tid;
        const float* qm = qmax4 + (size_t)gr*(Bp*4) + pb*4;
        float m4 = fmaxf(fmaxf(qm[0],qm[1]), fmaxf(qm[2],qm[3]));
        const float4* sp = (const float4*)(ssq_q + gr*16);
        float4 a0 = sp[0], a1 = sp[1], a2 = sp[2], a3 = sp[3];
        float t = ((a0.x+a0.y)+(a0.z+a0.w)) + ((a1.x+a1.y)+(a1.z+a1.w))
                + ((a2.x+a2.y)+(a2.z+a2.w)) + ((a3.x+a3.y)+(a3.z+a3.w));
        v  = m4 / fmaxf(sqrtf(t), 1e-12f);
        mm = q_mask[qb*Lq + tid + 1];
    }
    __shared__ float rv[128], rm[128];
    rv[tid]=v; rm[tid]=mm; __syncthreads();
    for (int o=64;o>0;o>>=1){ if (tid<o){ rv[tid]+=rv[tid+o]; rm[tid]+=rm[tid+o]; } __syncthreads(); }
    if (tid==0) out[2*Bq*Bp + qb*Bp+pb] = rv[0]/rm[0]*INV_TEMP;
}

/* ---------------- host: tensor-map creation via dlopen'd driver API ---------------- */
typedef CUresult (*EncFn)(CUtensorMap*, CUtensorMapDataType, cuuint32_t, void*,
                          const cuuint64_t*, const cuuint64_t*, const cuuint32_t*,
                          const cuuint32_t*, CUtensorMapInterleave, CUtensorMapSwizzle,
                          CUtensorMapL2promotion, CUtensorMapFloatOOBfill);

static void make_map2d(EncFn enc, CUtensorMap* m, void* addr, unsigned long long d0, unsigned long long d1){
    cuuint64_t dims[2]    = {(cuuint64_t)d0, (cuuint64_t)d1};
    cuuint64_t strides[1] = {(cuuint64_t)(d0*2)};
    cuuint32_t box[2]     = {(cuuint32_t)KS, 128u};
    cuuint32_t es[2]      = {1u, 1u};
    enc(m, CU_TENSOR_MAP_DATA_TYPE_BFLOAT16, 2, addr, dims, strides, box, es,
        CU_TENSOR_MAP_INTERLEAVE_NONE, CU_TENSOR_MAP_SWIZZLE_128B,
        CU_TENSOR_MAP_L2_PROMOTION_L2_128B, CU_TENSOR_MAP_FLOAT_OOB_FILL_NONE);
}

/* ---------------- launcher ---------------- */
extern "C" void kernel_launch(void* const* d_in, const int* in_sizes, int n_in,
                              void* d_out, int out_size)
{
    const float* q_hidden  = (const float*)d_in[0];
    const float* p_hidden  = (const float*)d_in[1];
    const float* q_mask    = (const float*)d_in[2];
    const float* p_mask    = (const float*)d_in[3];
    const int*   q_ids     = (const int*)  d_in[4];
    const int*   p_ids     = (const int*)  d_in[5];
    const float* colbert_w = (const float*)d_in[6];
    const float* colbert_b = (const float*)d_in[7];
    const float* sparse_w  = (const float*)d_in[8];
    const float* sparse_b  = (const float*)d_in[9];
    float* out = (float*)d_out;

    static float *p_tw_q=nullptr,*p_wq=nullptr,*p_tw_p=nullptr,*p_wp=nullptr,
                 *p_qmax=nullptr,*p_ssq_q=nullptr,*p_ssq_p=nullptr;
    static __nv_bfloat16 *p_qh=nullptr,*p_ph=nullptr,*p_w=nullptr,*p_Qcb=nullptr,*p_Pcb=nullptr;
    static CUtensorMap *pm_aq=nullptr,*pm_ap=nullptr,*pm_w=nullptr,*pm_q=nullptr,*pm_p=nullptr;
    static cudaStream_t s2 = nullptr;
    static cudaEvent_t ev0 = nullptr, evF = nullptr, evA = nullptr, evB = nullptr;
    if (!p_tw_q){
        cudaGetSymbolAddress((void**)&p_tw_q, g_tw_q);
        cudaGetSymbolAddress((void**)&p_wq,   g_wq);
        cudaGetSymbolAddress((void**)&p_tw_p, g_tw_p);
        cudaGetSymbolAddress((void**)&p_wp,   g_wp);
        cudaGetSymbolAddress((void**)&p_qmax, g_qmax);
        cudaGetSymbolAddress((void**)&p_ssq_q, g_ssq_q);
        cudaGetSymbolAddress((void**)&p_ssq_p, g_ssq_p);
        cudaGetSymbolAddress((void**)&p_qh,   g_qh_bf);
        cudaGetSymbolAddress((void**)&p_ph,   g_ph_bf);
        cudaGetSymbolAddress((void**)&p_w,    g_w_bf);
        cudaGetSymbolAddress((void**)&p_Qcb,  g_Qcb);
        cudaGetSymbolAddress((void**)&p_Pcb,  g_Pcb);
        cudaGetSymbolAddress((void**)&pm_aq,  g_map_aq);
        cudaGetSymbolAddress((void**)&pm_ap,  g_map_ap);
        cudaGetSymbolAddress((void**)&pm_w,   g_map_w);
        cudaGetSymbolAddress((void**)&pm_q,   g_map_q);
        cudaGetSymbolAddress((void**)&pm_p,   g_map_p);
        cudaFuncSetAttribute(proj_mma,   cudaFuncAttributeMaxDynamicSharedMemorySize, SMEM_TOTAL);
        cudaFuncSetAttribute(maxsim_mma, cudaFuncAttributeMaxDynamicSharedMemorySize, SMEM_TOTAL);
        cudaStreamCreateWithFlags(&s2, cudaStreamNonBlocking);
        cudaEventCreateWithFlags(&ev0, cudaEventDisableTiming);
        cudaEventCreateWithFlags(&evF, cudaEventDisableTiming);
        cudaEventCreateWithFlags(&evA, cudaEventDisableTiming);
        cudaEventCreateWithFlags(&evB, cudaEventDisableTiming);

        /* build tensor maps once (first, uncaptured call) */
        void* h = dlopen("libcuda.so.1", RTLD_NOW | RTLD_GLOBAL);
        if (!h) h = dlopen("libcuda.so", RTLD_NOW | RTLD_GLOBAL);
        EncFn enc = (EncFn)dlsym(h, "cuTensorMapEncodeTiled");
        CUtensorMap hm_aq, hm_ap, hm_w, hm_q, hm_p;
        make_map2d(enc, &hm_aq, p_qh,  Hd, MQ);
        make_map2d(enc, &hm_ap, p_ph,  Hd, MP);
        make_map2d(enc, &hm_w,  p_w,   Hd, Hd);
        make_map2d(enc, &hm_q,  p_Qcb, Hd, MQ);
        make_map2d(enc, &hm_p,  p_Pcb, Hd, MP);
        cudaMemcpyToSymbol(g_map_aq, &hm_aq, sizeof(CUtensorMap));
        cudaMemcpyToSymbol(g_map_ap, &hm_ap, sizeof(CUtensorMap));
        cudaMemcpyToSymbol(g_map_w,  &hm_w,  sizeof(CUtensorMap));
        cudaMemcpyToSymbol(g_map_q,  &hm_q,  sizeof(CUtensorMap));
        cudaMemcpyToSymbol(g_map_p,  &hm_p,  sizeof(CUtensorMap));
    }

    dim3 gQP(Bp, Bq);

    /* fork side stream at capture head: f2bf + dense depend only on raw inputs */
    cudaEventRecord(ev0, 0);
    cudaStreamWaitEvent(s2, ev0, 0);
    f2bf_kernel<<<(Hd*Hd/4 + 255)/256, 256, 0, s2>>>(colbert_w, p_w, Hd*Hd/4);
    cudaEventRecord(evF, s2);
    dense_kernel<<<gQP, 256, 0, s2>>>(q_hidden, p_hidden, out);

    /* main stream: converts (+ fused sparse token weights, compact bf16 layout) */
    cvt_tw_all<<<Bq*Lq + Bp*Lp, 128>>>(q_hidden, p_hidden, sparse_w, sparse_b,
                                       p_qh, p_ph, p_tw_q, p_tw_p);
    cudaEventRecord(evA, 0);

    /* main stream: GEMM chain (needs p_w from s2) */
    cudaStreamWaitEvent(0, evF, 0);
    proj_mma<<<dim3(Hd/128, QTILES+PTILES), 128, SMEM_TOTAL>>>(
        pm_aq, pm_ap, pm_w, p_Qcb, p_Pcb, p_ssq_q, p_ssq_p, colbert_b, q_mask, p_mask);
    maxsim_mma<<<dim3(Bp*4, QTILES), 128, SMEM_TOTAL>>>(pm_q, pm_p, p_ssq_p, p_qmax);

    /* side stream: sparse chain (needs tw from cvt on main) */
    cudaStreamWaitEvent(s2, evA, 0);
    canon_kernel<<<Bq, Lq, 0, s2>>>(q_ids, p_tw_q, p_wq, Lq);
    canon_kernel<<<Bp, Lp, 0, s2>>>(p_ids, p_tw_p, p_wp, Lp);
    sparse_score_kernel<<<gQP, 256, 0, s2>>>(q_ids, p_wq, p_ids, p_wp, out);
    cudaEventRecord(evB, s2);

    /* join + final */
    cudaStreamWaitEvent(0, evB, 0);
    colbert_final_kernel<<<gQP, 128>>>(p_qmax, p_ssq_q, q_mask, out);
}

// round 17
// speedup vs baseline: 1.1684x; 1.0140x over previous
#include <cuda_runtime.h>
#include <cuda.h>
#include <cuda_bf16.h>
#include <math.h>
#include <stdint.h>
#include <dlfcn.h>

#define Bq 8
#define Lq 128
#define Bp 64
#define Lp 512
#define Hd 1024
#define MQ (Bq*(Lq-1))   /* 1016  */
#define MP (Bp*(Lp-1))   /* 32704 */
#define QTILES 8
#define PTILES 256
#define INV_TEMP 50.0f

/* GEMM: block 128x128, 4 warps (2Mx2N), warp tile 64x64, K-stage 64,
   3-stage ring fed by one 2D TMA tile load per operand per stage.
   Producer/consumer mbarrier pairs: FB (tx-complete) + EB (128-arrive). */
#define KS   64
#define NSTG (Hd/KS)          /* 16 */
#define ROWB 128              /* SW128-swizzled rows */
#define TILEB (128*ROWB)      /* 16384 B */
#define STGB  (2*TILEB)       /* 32768 B */
#define NPIPE 3
#define RED_OFF  (NPIPE*STGB)      /* 98304 */
#define RSQP_OFF (RED_OFF + 1024)
#define MBAR_OFF (RSQP_OFF + 512)  /* FB0,FB1,FB2,EB0,EB1,EB2 (8B each) */
#define SMEM_TOTAL (MBAR_OFF + 64) /* ~99.9 KB -> 2 CTA/SM */

/* ---------------- scratch (allocation-free: device globals) ---------------- */
__device__ float g_tw_q[Bq*Lq];
__device__ float g_wq[Bq*Lq];
__device__ float g_tw_p[Bp*Lp];
__device__ float g_wp[Bp*Lp];
__device__ float g_qmax[(size_t)MQ*Bp*4];
__device__ float g_ssq_q[MQ*16];
__device__ float g_ssq_p[(size_t)MP*16];
__device__ float g_mkq[MQ];          /* compact CLS-dropped masks */
__device__ float g_mkp[MP];
__device__ __align__(256) __nv_bfloat16 g_qh_bf[(size_t)MQ*Hd];   /* compact, CLS dropped */
__device__ __align__(256) __nv_bfloat16 g_ph_bf[(size_t)MP*Hd];   /* compact, CLS dropped */
__device__ __align__(256) __nv_bfloat16 g_w_bf[(size_t)Hd*Hd];
__device__ __align__(256) __nv_bfloat16 g_Qcb[(size_t)MQ*Hd];
__device__ __align__(256) __nv_bfloat16 g_Pcb[(size_t)MP*Hd];
__device__ __align__(128) CUtensorMap g_map_aq, g_map_ap, g_map_w, g_map_q, g_map_p;

/* ---------------- helpers ---------------- */
__device__ __forceinline__ uint32_t sw128(uint32_t o){ return o ^ ((o>>3)&0x70u); }

__device__ __forceinline__ void mma_bf16(float* c, const unsigned* a, const unsigned* b){
    asm volatile("mma.sync.aligned.m16n8k16.row.col.f32.bf16.bf16.f32 "
        "{%0,%1,%2,%3}, {%4,%5,%6,%7}, {%8,%9}, {%0,%1,%2,%3};"
        : "+f"(c[0]), "+f"(c[1]), "+f"(c[2]), "+f"(c[3])
        : "r"(a[0]), "r"(a[1]), "r"(a[2]), "r"(a[3]), "r"(b[0]), "r"(b[1]));
}
__device__ __forceinline__ void ldm_x4(unsigned& r0, unsigned& r1, unsigned& r2, unsigned& r3, unsigned addr){
    asm volatile("ldmatrix.sync.aligned.m8n8.x4.shared.b16 {%0,%1,%2,%3}, [%4];"
        : "=r"(r0), "=r"(r1), "=r"(r2), "=r"(r3) : "r"(addr));
}
__device__ __forceinline__ void tma2d(unsigned dst, const CUtensorMap* map, int x, int y, unsigned mbar){
    asm volatile("cp.async.bulk.tensor.2d.shared::cluster.global.tile.mbarrier::complete_tx::bytes "
                 "[%0], [%1, {%2, %3}], [%4];"
                 :: "r"(dst), "l"(map), "r"(x), "r"(y), "r"(mbar) : "memory");
}
#define TMA_PREFETCH(map) asm volatile("prefetch.tensormap [%0];" :: "l"(map))
#define MBARRIER_INIT(addr, cnt) \
    asm volatile("mbarrier.init.shared.b64 [%0], %1;" :: "r"(addr), "r"(cnt) : "memory")
#define MBARRIER_EXPECT_TX(addr, bytes) \
    asm volatile("mbarrier.arrive.expect_tx.shared.b64 _, [%0], %1;" :: "r"(addr), "r"(bytes) : "memory")
#define MBARRIER_ARRIVE(addr) \
    asm volatile("mbarrier.arrive.shared.b64 _, [%0];" :: "r"(addr) : "memory")
#define MB_WAIT(mbar, parity) do{                                                   \
    uint32_t _done;                                                                 \
    asm volatile("{\n\t.reg .pred p;\n\t"                                           \
        "mbarrier.try_wait.parity.acquire.cta.shared::cta.b64 p, [%1], %2;\n\t"     \
        "selp.b32 %0, 1, 0, p;\n\t}" : "=r"(_done) : "r"(mbar), "r"(parity) : "memory"); \
    while(!_done){                                                                  \
        asm volatile("{\n\t.reg .pred p;\n\t"                                       \
            "mbarrier.try_wait.parity.acquire.cta.shared::cta.b64 p, [%1], %2, 0x989680;\n\t" \
            "selp.b32 %0, 1, 0, p;\n\t}" : "=r"(_done) : "r"(mbar), "r"(parity) : "memory"); \
    }                                                                               \
}while(0)
/* relaxed wait: producers only (post-wait accesses are async-proxy TMA) */
#define MB_WAIT_RLX(mbar, parity) do{                                               \
    uint32_t _done;                                                                 \
    asm volatile("{\n\t.reg .pred p;\n\t"                                           \
        "mbarrier.try_wait.parity.relaxed.cta.shared::cta.b64 p, [%1], %2, 0x989680;\n\t" \
        "selp.b32 %0, 1, 0, p;\n\t}" : "=r"(_done) : "r"(mbar), "r"(parity) : "memory"); \
    while(!_done){                                                                  \
        asm volatile("{\n\t.reg .pred p;\n\t"                                       \
            "mbarrier.try_wait.parity.relaxed.cta.shared::cta.b64 p, [%1], %2, 0x989680;\n\t" \
            "selp.b32 %0, 1, 0, p;\n\t}" : "=r"(_done) : "r"(mbar), "r"(parity) : "memory"); \
    }                                                                               \
}while(0)

/* K=64 stage for warp tile 64x64, SW128-swizzled smem: 8 ldsm.x4 -> 32 mma per k-step */
__device__ __forceinline__ void mma_stage64(unsigned abase, unsigned bbase,
                                            int lane, int wm, int wn, float acc[4][8][4])
{
    #pragma unroll
    for (int k=0;k<4;k++){
        int klo = k*16;
        unsigned a[4][4];
        int m_i = lane>>3;
        int arow = ((m_i&1)<<3) + (lane&7);
        int acol = klo + ((m_i>>1)<<3);
        #pragma unroll
        for (int mt=0; mt<4; mt++){
            unsigned addr = abase + sw128((unsigned)((wm*64 + mt*16 + arow)*ROWB + acol*2));
            ldm_x4(a[mt][0], a[mt][1], a[mt][2], a[mt][3], addr);
        }
        unsigned b[4][4];
        int brow = (lane&7) + ((lane>>4)<<3);
        int bcol = klo + (((lane>>3)&1)<<3);
        #pragma unroll
        for (int bpi=0; bpi<4; bpi++){
            unsigned addr = bbase + sw128((unsigned)((wn*64 + bpi*16 + brow)*ROWB + bcol*2));
            ldm_x4(b[bpi][0], b[bpi][1], b[bpi][2], b[bpi][3], addr);
        }
        #pragma unroll
        for (int mt=0; mt<4; mt++)
            #pragma unroll
            for (int nt=0; nt<8; nt++)
                mma_bf16(acc[mt][nt], a[mt], &b[nt>>1][(nt&1)*2]);
    }
}

/* ---------------- merged Q+P projection GEMM (TMA-fed), fused bias/mask epilogue ---------------- */
__global__ void __launch_bounds__(128,2)
proj_mma(const CUtensorMap* __restrict__ mapAq, const CUtensorMap* __restrict__ mapAp,
         const CUtensorMap* __restrict__ mapW,
         __nv_bfloat16* __restrict__ Cq, __nv_bfloat16* __restrict__ Cp,
         float* __restrict__ ssq_q, float* __restrict__ ssq_p,
         const float* __restrict__ bias,
         const float* __restrict__ mkq, const float* __restrict__ mkp)
{
    extern __shared__ __align__(1024) char smem[];
    unsigned sb = (unsigned)__cvta_generic_to_shared(smem);
    int tid = threadIdx.x, lane = tid&31, wid = tid>>5;
    int wm = wid>>1, wn = wid&1;

    bool isQ = blockIdx.y < QTILES;
    const CUtensorMap* mapA = isQ ? mapAq : mapAp;
    __nv_bfloat16* Cb = isQ ? Cq : Cp;
    float* ssq = isQ ? ssq_q : ssq_p;
    const float* mk = isQ ? mkq : mkp;
    int M  = isQ ? MQ : MP;
    int blkM = (isQ ? blockIdx.y : blockIdx.y - QTILES) * 128;
    int blkN = blockIdx.x*128;

    if (tid==0){
        TMA_PREFETCH(mapA);
        TMA_PREFETCH(mapW);
        MBARRIER_INIT(sb+MBAR_OFF,    1u);   /* FB0 */
        MBARRIER_INIT(sb+MBAR_OFF+8,  1u);   /* FB1 */
        MBARRIER_INIT(sb+MBAR_OFF+16, 1u);   /* FB2 */
        MBARRIER_INIT(sb+MBAR_OFF+24, 128u); /* EB0 */
        MBARRIER_INIT(sb+MBAR_OFF+32, 128u); /* EB1 */
        MBARRIER_INIT(sb+MBAR_OFF+40, 128u); /* EB2 */
    }
    __syncthreads();

    #define PROJ_ISSUE(bufi, stg) do{                                       \
        unsigned st_ = sb + (unsigned)(bufi)*STGB;                          \
        unsigned mb_ = sb + MBAR_OFF + (unsigned)(bufi)*8;                  \
        int k0_ = (stg)*KS;                                                 \
        MBARRIER_EXPECT_TX(mb_, (unsigned)STGB);                            \
        tma2d(st_,         mapA, k0_, blkM, mb_);                           \
        tma2d(st_ + TILEB, mapW, k0_, blkN, mb_);                           \
    }while(0)

    float acc[4][8][4];
    #pragma unroll
    for (int mt=0;mt<4;mt++) for (int nt=0;nt<8;nt++) for (int j=0;j<4;j++) acc[mt][nt][j]=0.f;

    if (tid==0){ PROJ_ISSUE(0, 0); PROJ_ISSUE(1, 1); }

    int eph0=0, eph1=0, eph2=0;
    #pragma unroll 1
    for (int s=0; s<NSTG; s++){
        if (s+2 < NSTG && tid==0){
            int b = (s+2)%NPIPE;
            if (s > 0){   /* buffer b was consumed in stage s-1; wait all 128 arrivals */
                if (b==0){ MB_WAIT_RLX(sb+MBAR_OFF+24, eph0); eph0^=1; }
                else if (b==1){ MB_WAIT_RLX(sb+MBAR_OFF+32, eph1); eph1^=1; }
                else { MB_WAIT_RLX(sb+MBAR_OFF+40, eph2); eph2^=1; }
            }
            PROJ_ISSUE(b, s+2);
        }
        int cbuf = s%NPIPE;
        int fph = (s/NPIPE)&1;
        MB_WAIT(sb + MBAR_OFF + (unsigned)cbuf*8, fph);
        unsigned cs = sb + (unsigned)cbuf*STGB;
        mma_stage64(cs, cs + TILEB, lane, wm, wn, acc);
        MBARRIER_ARRIVE(sb + MBAR_OFF + 24 + (unsigned)cbuf*8);
    }
    #undef PROJ_ISSUE

    /* epilogue: bias + compact mask, partial sumsq, bf16 store (unnormalized) */
    #pragma unroll
    for (int mt=0;mt<4;mt++){
        #pragma unroll
        for (int half=0; half<2; half++){
            int gr = blkM + wm*64 + mt*16 + (lane>>2) + half*8;
            bool valid = gr < M;
            float m = valid ? mk[gr] : 0.f;
            float ss = 0.f;
            #pragma unroll
            for (int nt=0;nt<8;nt++){
                int gc = blkN + wn*64 + nt*8 + 2*(lane&3);
                float2 bv2 = *(const float2*)(bias + gc);
                float v0 = (acc[mt][nt][half*2+0] + bv2.x) * m;
                float v1 = (acc[mt][nt][half*2+1] + bv2.y) * m;
                ss = fmaf(v0,v0, fmaf(v1,v1, ss));
                if (valid){
                    __nv_bfloat162 bv = __floats2bfloat162_rn(v0, v1);
                    *(__nv_bfloat162*)(Cb + (size_t)gr*Hd + gc) = bv;
                }
            }
            ss += __shfl_xor_sync(0xffffffffu, ss, 1);
            ss += __shfl_xor_sync(0xffffffffu, ss, 2);
            if (valid && (lane&3)==0)
                ssq[(size_t)gr*16 + blockIdx.x*2 + wn] = ss;
        }
    }
}

/* ---------------- maxsim GEMM (quarter-split, TMA-fed) with fused p-norm scaling ---------------- */
__global__ void __launch_bounds__(128,2)
maxsim_mma(const CUtensorMap* __restrict__ mapQ, const CUtensorMap* __restrict__ mapP,
           const float* __restrict__ ssq_p, float* __restrict__ qmax4)
{
    extern __shared__ __align__(1024) char smem[];
    unsigned sb = (unsigned)__cvta_generic_to_shared(smem);
    float* red  = (float*)(smem + RED_OFF);
    float* rsqs = (float*)(smem + RSQP_OFF);
    int tid = threadIdx.x, lane = tid&31, wid = tid>>5;
    int wm = wid>>1, wn = wid&1;
    int pbi = blockIdx.x>>2, qc = blockIdx.x&3;
    int blkM = blockIdx.y*128;
    int brow0 = pbi*(Lp-1) + qc*128;

    int bvv = (Lp-1) - qc*128; if (bvv > 128) bvv = 128;

    if (tid==0){
        TMA_PREFETCH(mapQ);
        TMA_PREFETCH(mapP);
        MBARRIER_INIT(sb+MBAR_OFF,    1u);
        MBARRIER_INIT(sb+MBAR_OFF+8,  1u);
        MBARRIER_INIT(sb+MBAR_OFF+16, 1u);
        MBARRIER_INIT(sb+MBAR_OFF+24, 128u);
        MBARRIER_INIT(sb+MBAR_OFF+32, 128u);
        MBARRIER_INIT(sb+MBAR_OFF+40, 128u);
    }
    /* per-passage-token reciprocal norms into smem (overlaps pipeline fill) */
    if (tid < bvv){
        const float4* sp = (const float4*)(ssq_p + ((long)brow0 + tid)*16);
        float4 a0 = sp[0], a1 = sp[1], a2 = sp[2], a3 = sp[3];
        float t = ((a0.x+a0.y)+(a0.z+a0.w)) + ((a1.x+a1.y)+(a1.z+a1.w))
                + ((a2.x+a2.y)+(a2.z+a2.w)) + ((a3.x+a3.y)+(a3.z+a3.w));
        rsqs[tid] = 1.0f / fmaxf(sqrtf(t), 1e-12f);
    }
    __syncthreads();

    #define MS_ISSUE(bufi, stg) do{                                         \
        unsigned st_ = sb + (unsigned)(bufi)*STGB;                          \
        unsigned mb_ = sb + MBAR_OFF + (unsigned)(bufi)*8;                  \
        int k0_ = (stg)*KS;                                                 \
        MBARRIER_EXPECT_TX(mb_, (unsigned)STGB);                            \
        tma2d(st_,         mapQ, k0_, blkM,  mb_);                          \
        tma2d(st_ + TILEB, mapP, k0_, brow0, mb_);                          \
    }while(0)

    float acc[4][8][4];
    #pragma unroll
    for (int mt=0;mt<4;mt++) for (int nt=0;nt<8;nt++) for (int j=0;j<4;j++) acc[mt][nt][j]=0.f;

    if (tid==0){ MS_ISSUE(0, 0); MS_ISSUE(1, 1); }

    int eph0=0, eph1=0, eph2=0;
    #pragma unroll 1
    for (int s=0; s<NSTG; s++){
        if (s+2 < NSTG && tid==0){
            int b = (s+2)%NPIPE;
            if (s > 0){
                if (b==0){ MB_WAIT_RLX(sb+MBAR_OFF+24, eph0); eph0^=1; }
                else if (b==1){ MB_WAIT_RLX(sb+MBAR_OFF+32, eph1); eph1^=1; }
                else { MB_WAIT_RLX(sb+MBAR_OFF+40, eph2); eph2^=1; }
            }
            MS_ISSUE(b, s+2);
        }
        int cbuf = s%NPIPE;
        int fph = (s/NPIPE)&1;
        MB_WAIT(sb + MBAR_OFF + (unsigned)cbuf*8, fph);
        unsigned cs = sb + (unsigned)cbuf*STGB;
        mma_stage64(cs, cs + TILEB, lane, wm, wn, acc);
        MBARRIER_ARRIVE(sb + MBAR_OFF + 24 + (unsigned)cbuf*8);
    }
    #undef MS_ISSUE

    /* fold: apply per-token reciprocal norm, then running max */
    float runmax[4][2];
    #pragma unroll
    for (int mt=0;mt<4;mt++){ runmax[mt][0]=-1e30f; runmax[mt][1]=-1e30f; }
    #pragma unroll
    for (int nt=0;nt<8;nt++){
        int c0 = wn*64 + nt*8 + 2*(lane&3);
        bool v0 = c0     < bvv;
        bool v1 = c0 + 1 < bvv;
        float sp0 = v0 ? rsqs[c0]   : 0.f;
        float sp1 = v1 ? rsqs[c0+1] : 0.f;
        #pragma unroll
        for (int mt=0;mt<4;mt++){
            if (v0){
                runmax[mt][0] = fmaxf(runmax[mt][0], acc[mt][nt][0]*sp0);
                runmax[mt][1] = fmaxf(runmax[mt][1], acc[mt][nt][2]*sp0);
            }
            if (v1){
                runmax[mt][0] = fmaxf(runmax[mt][0], acc[mt][nt][1]*sp1);
                runmax[mt][1] = fmaxf(runmax[mt][1], acc[mt][nt][3]*sp1);
            }
        }
    }

    #pragma unroll
    for (int mt=0;mt<4;mt++){
        #pragma unroll
        for (int h=0;h<2;h++){
            runmax[mt][h] = fmaxf(runmax[mt][h], __shfl_xor_sync(0xffffffffu, runmax[mt][h], 1));
            runmax[mt][h] = fmaxf(runmax[mt][h], __shfl_xor_sync(0xffffffffu, runmax[mt][h], 2));
        }
    }
    if ((lane&3)==0){
        #pragma unroll
        for (int mt=0;mt<4;mt++){
            int row = wm*64 + mt*16 + (lane>>2);
            red[row*2 + wn]     = runmax[mt][0];
            red[(row+8)*2 + wn] = runmax[mt][1];
        }
    }
    __syncthreads();
    {
        int gr = blkM + tid;
        if (gr < MQ)
            qmax4[(size_t)gr*(Bp*4) + blockIdx.x] = fmaxf(red[tid*2], red[tid*2+1]);
    }
}

/* ---------------- merged f32->bf16 convert (compact) + sparse tw + compact masks ---------------- */
__global__ void cvt_tw_all(const float* __restrict__ qh, const float* __restrict__ ph,
                           const float* __restrict__ q_mask, const float* __restrict__ p_mask,
                           const float* __restrict__ sw, const float* __restrict__ sbp,
                           __nv_bfloat16* __restrict__ qbf, __nv_bfloat16* __restrict__ pbf,
                           float* __restrict__ twq, float* __restrict__ twp,
                           float* __restrict__ mkq, float* __restrict__ mkp)
{
    int row = blockIdx.x, tid = threadIdx.x;
    int lane = tid&31, wid = tid>>5;
    const float* h; const float* msk; __nv_bfloat16* o; float* tw; float* mk; int r, L;
    if (row < Bq*Lq){ h = qh; msk = q_mask; o = qbf; tw = twq; mk = mkq; r = row; L = Lq; }
    else            { r = row - Bq*Lq; h = ph; msk = p_mask; o = pbf; tw = twp; mk = mkp; L = Lp; }
    int b = r / L, t = r % L;
    const float* hp = h + (size_t)r*Hd + tid*8;
    float4 a = *(const float4*)hp;
    float4 bb = *(const float4*)(hp+4);
    const float* w = sw + tid*8;
    float4 wa = *(const float4*)w;
    float4 wb = *(const float4*)(w+4);
    if (t > 0){
        int cr = b*(L-1) + (t-1);
        uint4 ov;
        __nv_bfloat162 p0 = __floats2bfloat162_rn(a.x, a.y);
        __nv_bfloat162 p1 = __floats2bfloat162_rn(a.z, a.w);
        __nv_bfloat162 p2 = __floats2bfloat162_rn(bb.x, bb.y);
        __nv_bfloat162 p3 = __floats2bfloat162_rn(bb.z, bb.w);
        ov.x = *(unsigned*)&p0; ov.y = *(unsigned*)&p1; ov.z = *(unsigned*)&p2; ov.w = *(unsigned*)&p3;
        *(uint4*)(o + (size_t)cr*Hd + tid*8) = ov;
        if (tid==0) mk[cr] = msk[r];
    }
    float s = fmaf(a.x,wa.x, fmaf(a.y,wa.y, fmaf(a.z,wa.z, fmaf(a.w,wa.w,
              fmaf(bb.x,wb.x, fmaf(bb.y,wb.y, fmaf(bb.z,wb.z, bb.w*wb.w)))))));
    #pragma unroll
    for (int of=16;of;of>>=1) s += __shfl_xor_sync(0xffffffffu, s, of);
    __shared__ float ws[4];
    if (lane==0) ws[wid] = s;
    __syncthreads();
    if (tid==0) tw[r] = fmaxf(ws[0]+ws[1]+ws[2]+ws[3] + sbp[0], 0.f);
}

/* ---------------- f32 -> bf16 convert (weights only) ---------------- */
__global__ void f2bf_kernel(const float* __restrict__ in, __nv_bfloat16* __restrict__ out, int n4){
    int i = blockIdx.x*blockDim.x + threadIdx.x;
    if (i < n4){
        float4 v = *(const float4*)(in + (size_t)i*4);
        __nv_bfloat162 lo = __floats2bfloat162_rn(v.x, v.y);
        __nv_bfloat162 hi = __floats2bfloat162_rn(v.z, v.w);
        uint2 o; o.x = *(unsigned*)&lo; o.y = *(unsigned*)&hi;
        *(uint2*)(out + (size_t)i*4) = o;
    }
}

/* ---------------- dense: CLS cosine / TEMP ---------------- */
__global__ void dense_kernel(const float* __restrict__ qh, const float* __restrict__ ph,
                             float* __restrict__ out)
{
    int pb = blockIdx.x, qb = blockIdx.y, tid = threadIdx.x;
    const float* q = qh + (size_t)qb*Lq*Hd;
    const float* p = ph + (size_t)pb*Lp*Hd;
    float qq=0.f, pp=0.f, qp=0.f;
    for (int i=tid;i<Hd;i+=256){ float a=q[i], b=p[i];
        qq=fmaf(a,a,qq); pp=fmaf(b,b,pp); qp=fmaf(a,b,qp); }
    __shared__ float r0[256], r1[256], r2[256];
    r0[tid]=qq; r1[tid]=pp; r2[tid]=qp; __syncthreads();
    for (int o=128;o>0;o>>=1){
        if (tid<o){ r0[tid]+=r0[tid+o]; r1[tid]+=r1[tid+o]; r2[tid]+=r2[tid+o]; }
        __syncthreads();
    }
    if (tid==0){
        float d = fmaxf(sqrtf(r0[0]),1e-12f)*fmaxf(sqrtf(r1[0]),1e-12f);
        out[qb*Bp+pb] = r2[0]/d*INV_TEMP;
    }
}

/* ---------------- sparse dedup + scoring ---------------- */
__global__ void canon_kernel(const int* __restrict__ ids, const float* __restrict__ tw,
                             float* __restrict__ weff, int L)
{
    __shared__ int   sid[512];
    __shared__ float stw[512];
    int b = blockIdx.x, i = threadIdx.x;
    int base = b*L;
    sid[i] = ids[base+i]; stw[i] = tw[base+i];
    __syncthreads();
    float w = stw[i]; int id = sid[i];
    if (id < 4) w = 0.f;
    else {
        for (int j=0;j<L;j++){
            if (j!=i && sid[j]==id){
                float wj = stw[j];
                if (wj > w || (wj==w && j<i)) { w=0.f; break; }
            }
        }
    }
    weff[base+i] = w;
}

__global__ void sparse_score_kernel(const int* __restrict__ q_ids, const float* __restrict__ wq,
                                    const int* __restrict__ p_ids, const float* __restrict__ wp,
                                    float* __restrict__ out)
{
    __shared__ int   spid[Lp];
    __shared__ float spw[Lp];
    __shared__ float red[256];
    int pb=blockIdx.x, qb=blockIdx.y, tid=threadIdx.x;
    for (int j=tid;j<Lp;j+=256){ spid[j]=p_ids[pb*Lp+j]; spw[j]=wp[pb*Lp+j]; }
    __syncthreads();
    float s = 0.f;
    if (tid < Lq){
        int id = q_ids[qb*Lq+tid]; float w = wq[qb*Lq+tid];
        if (w > 0.f){
            for (int j=0;j<Lp;j++) if (spid[j]==id) s = fmaf(w, spw[j], s);
        }
    }
    red[tid]=s; __syncthreads();
    for (int o=128;o>0;o>>=1){ if (tid<o) red[tid]+=red[tid+o]; __syncthreads(); }
    if (tid==0) out[Bq*Bp + qb*Bp+pb] = red[0]*INV_TEMP;
}

__global__ void colbert_final_kernel(const float* __restrict__ qmax4,
                                     const float* __restrict__ ssq_q,
                                     const float* __restrict__ q_mask,
                                     float* __restrict__ out)
{
    int pb=blockIdx.x, qb=blockIdx.y, tid=threadIdx.x;  /* 128 threads */
    float v=0.f, mm=0.f;
    if (tid < Lq-1){
        int gr = qb*(Lq-1)+tid;
        const float* qm = qmax4 + (size_t)gr*(Bp*4) + pb*4;
        float m4 = fmaxf(fmaxf(qm[0],qm[1]), fmaxf(qm[2],qm[3]));
        const float4* sp = (const float4*)(ssq_q + gr*16);
        float4 a0 = sp[0], a1 = sp[1], a2 = sp[2], a3 = sp[3];
        float t = ((a0.x+a0.y)+(a0.z+a0.w)) + ((a1.x+a1.y)+(a1.z+a1.w))
                + ((a2.x+a2.y)+(a2.z+a2.w)) + ((a3.x+a3.y)+(a3.z+a3.w));
        v  = m4 / fmaxf(sqrtf(t), 1e-12f);
        mm = q_mask[qb*Lq + tid + 1];
    }
    __shared__ float rv[128], rm[128];
    rv[tid]=v; rm[tid]=mm; __syncthreads();
    for (int o=64;o>0;o>>=1){ if (tid<o){ rv[tid]+=rv[tid+o]; rm[tid]+=rm[tid+o]; } __syncthreads(); }
    if (tid==0) out[2*Bq*Bp + qb*Bp+pb] = rv[0]/rm[0]*INV_TEMP;
}

/* ---------------- host: tensor-map creation via dlopen'd driver API ---------------- */
typedef CUresult (*EncFn)(CUtensorMap*, CUtensorMapDataType, cuuint32_t, void*,
                          const cuuint64_t*, const cuuint64_t*, const cuuint32_t*,
                          const cuuint32_t*, CUtensorMapInterleave, CUtensorMapSwizzle,
                          CUtensorMapL2promotion, CUtensorMapFloatOOBfill);

static void make_map2d(EncFn enc, CUtensorMap* m, void* addr, unsigned long long d0, unsigned long long d1){
    cuuint64_t dims[2]    = {(cuuint64_t)d0, (cuuint64_t)d1};
    cuuint64_t strides[1] = {(cuuint64_t)(d0*2)};
    cuuint32_t box[2]     = {(cuuint32_t)KS, 128u};
    cuuint32_t es[2]      = {1u, 1u};
    enc(m, CU_TENSOR_MAP_DATA_TYPE_BFLOAT16, 2, addr, dims, strides, box, es,
        CU_TENSOR_MAP_INTERLEAVE_NONE, CU_TENSOR_MAP_SWIZZLE_128B,
        CU_TENSOR_MAP_L2_PROMOTION_L2_128B, CU_TENSOR_MAP_FLOAT_OOB_FILL_NONE);
}

/* ---------------- launcher ---------------- */
extern "C" void kernel_launch(void* const* d_in, const int* in_sizes, int n_in,
                              void* d_out, int out_size)
{
    const float* q_hidden  = (const float*)d_in[0];
    const float* p_hidden  = (const float*)d_in[1];
    const float* q_mask    = (const float*)d_in[2];
    const float* p_mask    = (const float*)d_in[3];
    const int*   q_ids     = (const int*)  d_in[4];
    const int*   p_ids     = (const int*)  d_in[5];
    const float* colbert_w = (const float*)d_in[6];
    const float* colbert_b = (const float*)d_in[7];
    const float* sparse_w  = (const float*)d_in[8];
    const float* sparse_b  = (const float*)d_in[9];
    float* out = (float*)d_out;

    static float *p_tw_q=nullptr,*p_wq=nullptr,*p_tw_p=nullptr,*p_wp=nullptr,
                 *p_qmax=nullptr,*p_ssq_q=nullptr,*p_ssq_p=nullptr,*p_mkq=nullptr,*p_mkp=nullptr;
    static __nv_bfloat16 *p_qh=nullptr,*p_ph=nullptr,*p_w=nullptr,*p_Qcb=nullptr,*p_Pcb=nullptr;
    static CUtensorMap *pm_aq=nullptr,*pm_ap=nullptr,*pm_w=nullptr,*pm_q=nullptr,*pm_p=nullptr;
    static cudaStream_t s2 = nullptr;
    static cudaEvent_t ev0 = nullptr, evF = nullptr, evA = nullptr, evB = nullptr;
    if (!p_tw_q){
        cudaGetSymbolAddress((void**)&p_tw_q, g_tw_q);
        cudaGetSymbolAddress((void**)&p_wq,   g_wq);
        cudaGetSymbolAddress((void**)&p_tw_p, g_tw_p);
        cudaGetSymbolAddress((void**)&p_wp,   g_wp);
        cudaGetSymbolAddress((void**)&p_qmax, g_qmax);
        cudaGetSymbolAddress((void**)&p_ssq_q, g_ssq_q);
        cudaGetSymbolAddress((void**)&p_ssq_p, g_ssq_p);
        cudaGetSymbolAddress((void**)&p_mkq,  g_mkq);
        cudaGetSymbolAddress((void**)&p_mkp,  g_mkp);
        cudaGetSymbolAddress((void**)&p_qh,   g_qh_bf);
        cudaGetSymbolAddress((void**)&p_ph,   g_ph_bf);
        cudaGetSymbolAddress((void**)&p_w,    g_w_bf);
        cudaGetSymbolAddress((void**)&p_Qcb,  g_Qcb);
        cudaGetSymbolAddress((void**)&p_Pcb,  g_Pcb);
        cudaGetSymbolAddress((void**)&pm_aq,  g_map_aq);
        cudaGetSymbolAddress((void**)&pm_ap,  g_map_ap);
        cudaGetSymbolAddress((void**)&pm_w,   g_map_w);
        cudaGetSymbolAddress((void**)&pm_q,   g_map_q);
        cudaGetSymbolAddress((void**)&pm_p,   g_map_p);
        cudaFuncSetAttribute(proj_mma,   cudaFuncAttributeMaxDynamicSharedMemorySize, SMEM_TOTAL);
        cudaFuncSetAttribute(maxsim_mma, cudaFuncAttributeMaxDynamicSharedMemorySize, SMEM_TOTAL);
        cudaStreamCreateWithFlags(&s2, cudaStreamNonBlocking);
        cudaEventCreateWithFlags(&ev0, cudaEventDisableTiming);
        cudaEventCreateWithFlags(&evF, cudaEventDisableTiming);
        cudaEventCreateWithFlags(&evA, cudaEventDisableTiming);
        cudaEventCreateWithFlags(&evB, cudaEventDisableTiming);

        /* build tensor maps once (first, uncaptured call) */
        void* h = dlopen("libcuda.so.1", RTLD_NOW | RTLD_GLOBAL);
        if (!h) h = dlopen("libcuda.so", RTLD_NOW | RTLD_GLOBAL);
        EncFn enc = (EncFn)dlsym(h, "cuTensorMapEncodeTiled");
        CUtensorMap hm_aq, hm_ap, hm_w, hm_q, hm_p;
        make_map2d(enc, &hm_aq, p_qh,  Hd, MQ);
        make_map2d(enc, &hm_ap, p_ph,  Hd, MP);
        make_map2d(enc, &hm_w,  p_w,   Hd, Hd);
        make_map2d(enc, &hm_q,  p_Qcb, Hd, MQ);
        make_map2d(enc, &hm_p,  p_Pcb, Hd, MP);
        cudaMemcpyToSymbol(g_map_aq, &hm_aq, sizeof(CUtensorMap));
        cudaMemcpyToSymbol(g_map_ap, &hm_ap, sizeof(CUtensorMap));
        cudaMemcpyToSymbol(g_map_w,  &hm_w,  sizeof(CUtensorMap));
        cudaMemcpyToSymbol(g_map_q,  &hm_q,  sizeof(CUtensorMap));
        cudaMemcpyToSymbol(g_map_p,  &hm_p,  sizeof(CUtensorMap));
    }

    dim3 gQP(Bp, Bq);

    /* fork side stream at capture head: f2bf + dense depend only on raw inputs */
    cudaEventRecord(ev0, 0);
    cudaStreamWaitEvent(s2, ev0, 0);
    f2bf_kernel<<<(Hd*Hd/4 + 255)/256, 256, 0, s2>>>(colbert_w, p_w, Hd*Hd/4);
    cudaEventRecord(evF, s2);
    dense_kernel<<<gQP, 256, 0, s2>>>(q_hidden, p_hidden, out);

    /* main stream: converts (+ fused sparse token weights + compact masks) */
    cvt_tw_all<<<Bq*Lq + Bp*Lp, 128>>>(q_hidden, p_hidden, q_mask, p_mask,
                                       sparse_w, sparse_b,
                                       p_qh, p_ph, p_tw_q, p_tw_p, p_mkq, p_mkp);
    cudaEventRecord(evA, 0);

    /* main stream: GEMM chain (needs p_w from s2) */
    cudaStreamWaitEvent(0, evF, 0);
    proj_mma<<<dim3(Hd/128, QTILES+PTILES), 128, SMEM_TOTAL>>>(
        pm_aq, pm_ap, pm_w, p_Qcb, p_Pcb, p_ssq_q, p_ssq_p, colbert_b, p_mkq, p_mkp);
    maxsim_mma<<<dim3(Bp*4, QTILES), 128, SMEM_TOTAL>>>(pm_q, pm_p, p_ssq_p, p_qmax);

    /* side stream: sparse chain (needs tw from cvt on main) */
    cudaStreamWaitEvent(s2, evA, 0);
    canon_kernel<<<Bq, Lq, 0, s2>>>(q_ids, p_tw_q, p_wq, Lq);
    canon_kernel<<<Bp, Lp, 0, s2>>>(p_ids, p_tw_p, p_wp, Lp);
    sparse_score_kernel<<<gQP, 256, 0, s2>>>(q_ids, p_wq, p_ids, p_wp, out);
    cudaEventRecord(evB, s2);

    /* join + final */
    cudaStreamWaitEvent(0, evB, 0);
    colbert_final_kernel<<<gQP, 128>>>(p_qmax, p_ssq_q, q_mask, out);
}